// round 4
// baseline (speedup 1.0000x reference)
#include <cuda_runtime.h>
#include <cuda_bf16.h>
#include <cstdint>

#define B_SZ 2
#define SEQ 2048
#define ROWS (B_SZ * SEQ)          // 4096
#define D_MODEL 128
#define D_INNER 1024
#define NHEADS 8
#define HEADDIM 128
#define D_STATE 128
#define D_CONV 4
#define CONV_DIM (D_INNER + 2 * D_STATE)   // 1280
#define D_IN_PROJ (2 * D_INNER + 2 * D_STATE + NHEADS)  // 2312
#define EPS 1e-5f

#define QC 64                      // chunk length
#define NCH (SEQ / QC)             // 32 chunks
#define NBH (B_SZ * NHEADS)        // 16

// ---------------- scratch (no allocations allowed) ----------------
__device__ float g_h1[ROWS * D_MODEL];
__device__ float g_zx[ROWS * D_IN_PROJ];
__device__ float g_xbc[ROWS * CONV_DIM];
__device__ float g_dtT[NBH * SEQ];
__device__ float g_dtAT[NBH * SEQ];
__device__ float g_G[B_SZ * NCH * QC * QC];
__device__ float g_T[NBH * NCH * HEADDIM * D_STATE];
__device__ float g_Sp[NBH * NCH * HEADDIM * D_STATE];
__device__ float g_Lam[NBH * NCH];
__device__ float g_y[ROWS * D_INNER];
__device__ float g_g[ROWS * D_INNER];
__device__ float g_res2[ROWS * D_MODEL];
__device__ float g_h2[ROWS * D_MODEL];

__device__ __forceinline__ float siluf(float v) {
    return v / (1.0f + expf(-v));
}

// ---------------- tf32 helpers ----------------
__device__ __forceinline__ void tf32_split(float f, float& hi, float& lo) {
    uint32_t h;
    asm("cvt.rna.tf32.f32 %0, %1;" : "=r"(h) : "f"(f));
    float hf = __uint_as_float(h);
    float r = f - hf;
    uint32_t l;
    asm("cvt.rna.tf32.f32 %0, %1;" : "=r"(l) : "f"(r));
    hi = hf;
    lo = __uint_as_float(l);
}

__device__ __forceinline__ void mma_tf32(float* d,
    uint32_t a0, uint32_t a1, uint32_t a2, uint32_t a3,
    uint32_t b0, uint32_t b1)
{
    asm volatile(
        "mma.sync.aligned.m16n8k8.row.col.f32.tf32.tf32.f32 "
        "{%0,%1,%2,%3},{%4,%5,%6,%7},{%8,%9},{%0,%1,%2,%3};"
        : "+f"(d[0]), "+f"(d[1]), "+f"(d[2]), "+f"(d[3])
        : "r"(a0), "r"(a1), "r"(a2), "r"(a3), "r"(b0), "r"(b1));
}

// ---------------- LayerNorm ----------------
__global__ __launch_bounds__(128) void ln_kernel(
    const float* __restrict__ x, const float* __restrict__ w,
    const float* __restrict__ b, float* __restrict__ out)
{
    int row = blockIdx.x;
    int tid = threadIdx.x;
    __shared__ float sm[4];
    float v = x[(size_t)row * D_MODEL + tid];

    float s = v;
    #pragma unroll
    for (int o = 16; o; o >>= 1) s += __shfl_xor_sync(0xffffffffu, s, o);
    if ((tid & 31) == 0) sm[tid >> 5] = s;
    __syncthreads();
    float mean = (sm[0] + sm[1] + sm[2] + sm[3]) * (1.0f / 128.0f);
    __syncthreads();

    float d = v - mean;
    float q = d * d;
    #pragma unroll
    for (int o = 16; o; o >>= 1) q += __shfl_xor_sync(0xffffffffu, q, o);
    if ((tid & 31) == 0) sm[tid >> 5] = q;
    __syncthreads();
    float var = (sm[0] + sm[1] + sm[2] + sm[3]) * (1.0f / 128.0f);

    out[(size_t)row * D_MODEL + tid] = d * rsqrtf(var + EPS) * w[tid] + b[tid];
}

// ---------------- tensor-core GEMM (3xTF32): C = A[M,K] @ W[N,K]^T ----------
// block tile 128x64, 8 warps (4x2), warp tile 32x32 (2x4 m16n8k8 tiles).
// smem: fragments pre-permuted at stage time; conflict-free LDS.128/LDS.64.
// AF: [hl2][ks4][mt8][lane32][reg4] = 8192 floats
// BF: [hl2][ks4][nt8][lane32][reg2] = 4096 floats
template<bool RESID, bool BIAS>
__global__ __launch_bounds__(256) void gemm_mma(
    const float* __restrict__ A, int lda,
    const float* __restrict__ W, int ldw,
    float* __restrict__ C, int ldc,
    int N, int K,
    const float* __restrict__ resid,
    const float* __restrict__ bias)
{
    extern __shared__ float sm[];
    float* AF = sm;            // 8192
    float* BF = sm + 8192;     // 4096

    const int tid = threadIdx.x;
    const int lane = tid & 31;
    const int warp = tid >> 5;
    const int wm = warp >> 1;          // 0..3
    const int wn = warp & 1;           // 0..1
    const int m0 = blockIdx.y * 128;
    const int n0 = blockIdx.x * 64;

    float acc[2][4][4];
    #pragma unroll
    for (int mi = 0; mi < 2; mi++)
        #pragma unroll
        for (int ni = 0; ni < 4; ni++)
            #pragma unroll
            for (int r = 0; r < 4; r++) acc[mi][ni][r] = 0.f;

    for (int k0 = 0; k0 < K; k0 += 32) {
        // ---- stage A: 128 x 32 ----
        #pragma unroll
        for (int it = 0; it < 4; it++) {
            int i = tid + it * 256;            // 0..1023
            int m = i >> 3;
            int k4 = (i & 7) * 4;
            float4 av = *(const float4*)(A + (size_t)(m0 + m) * lda + k0 + k4);
            int mt = m >> 4;
            int r = m & 15;
            int lreg_base = ((r & 7) << 2);
            int rhalf = (r >> 3) & 1;
            #pragma unroll
            for (int l = 0; l < 4; l++) {
                int k = k4 + l;
                int ks = k >> 3;
                int c = k & 7;
                int ln = lreg_base | (c & 3);
                int reg = rhalf | ((c >> 2) << 1);
                float hi, lo;
                tf32_split((&av.x)[l], hi, lo);
                int idx = ((ks) * 8 + mt) * 128 + ln * 4 + reg;
                AF[idx] = hi;
                AF[4096 + idx] = lo;
            }
        }
        // ---- stage B: 64 x 32 ----
        #pragma unroll
        for (int it = 0; it < 2; it++) {
            int i = tid + it * 256;            // 0..511
            int n = i >> 3;
            int k4 = (i & 7) * 4;
            int wr = n0 + n;
            float4 wv = make_float4(0.f, 0.f, 0.f, 0.f);
            if (wr < N) wv = *(const float4*)(W + (size_t)wr * ldw + k0 + k4);
            int nt = n >> 3;
            int g = n & 7;
            #pragma unroll
            for (int l = 0; l < 4; l++) {
                int k = k4 + l;
                int ks = k >> 3;
                int c = k & 7;
                int ln = (g << 2) | (c & 3);
                int reg = (c >> 2);
                float hi, lo;
                tf32_split((&wv.x)[l], hi, lo);
                int idx = (ks * 8 + nt) * 64 + ln * 2 + reg;
                BF[idx] = hi;
                BF[2048 + idx] = lo;
            }
        }
        __syncthreads();

        #pragma unroll
        for (int ks = 0; ks < 4; ks++) {
            uint32_t ah[2][4], al[2][4], bh[4][2], bl[4][2];
            #pragma unroll
            for (int mi = 0; mi < 2; mi++) {
                int mt = wm * 2 + mi;
                float4 vh = *(const float4*)&AF[(ks * 8 + mt) * 128 + lane * 4];
                float4 vl = *(const float4*)&AF[4096 + (ks * 8 + mt) * 128 + lane * 4];
                #pragma unroll
                for (int r = 0; r < 4; r++) {
                    ah[mi][r] = __float_as_uint((&vh.x)[r]);
                    al[mi][r] = __float_as_uint((&vl.x)[r]);
                }
            }
            #pragma unroll
            for (int ni = 0; ni < 4; ni++) {
                int nt = wn * 4 + ni;
                float2 vh = *(const float2*)&BF[(ks * 8 + nt) * 64 + lane * 2];
                float2 vl = *(const float2*)&BF[2048 + (ks * 8 + nt) * 64 + lane * 2];
                bh[ni][0] = __float_as_uint(vh.x);
                bh[ni][1] = __float_as_uint(vh.y);
                bl[ni][0] = __float_as_uint(vl.x);
                bl[ni][1] = __float_as_uint(vl.y);
            }
            #pragma unroll
            for (int mi = 0; mi < 2; mi++)
                #pragma unroll
                for (int ni = 0; ni < 4; ni++) {
                    mma_tf32(acc[mi][ni], ah[mi][0], ah[mi][1], ah[mi][2], ah[mi][3],
                             bh[ni][0], bh[ni][1]);
                    mma_tf32(acc[mi][ni], ah[mi][0], ah[mi][1], ah[mi][2], ah[mi][3],
                             bl[ni][0], bl[ni][1]);
                    mma_tf32(acc[mi][ni], al[mi][0], al[mi][1], al[mi][2], al[mi][3],
                             bh[ni][0], bh[ni][1]);
                }
        }
        __syncthreads();
    }

    // ---- epilogue ----
    const int g = lane >> 2;
    const int tq = lane & 3;
    #pragma unroll
    for (int mi = 0; mi < 2; mi++) {
        #pragma unroll
        for (int ni = 0; ni < 4; ni++) {
            int row = m0 + wm * 32 + mi * 16 + g;
            int col = n0 + wn * 32 + ni * 8 + tq * 2;
            if (col < N) {
                float2 v0 = make_float2(acc[mi][ni][0], acc[mi][ni][1]);
                float2 v1 = make_float2(acc[mi][ni][2], acc[mi][ni][3]);
                if (RESID) {
                    float2 r0 = *(const float2*)(resid + (size_t)row * ldc + col);
                    float2 r1 = *(const float2*)(resid + (size_t)(row + 8) * ldc + col);
                    v0.x += r0.x; v0.y += r0.y;
                    v1.x += r1.x; v1.y += r1.y;
                }
                if (BIAS) {
                    float2 bb = *(const float2*)(bias + col);
                    v0.x += bb.x; v0.y += bb.y;
                    v1.x += bb.x; v1.y += bb.y;
                }
                *(float2*)(C + (size_t)row * ldc + col) = v0;
                *(float2*)(C + (size_t)(row + 8) * ldc + col) = v1;
            }
        }
    }
}

// ---------------- depthwise causal conv (k=4) + bias + silu ----------------
__global__ __launch_bounds__(256) void conv_kernel(
    const float* __restrict__ zx, const float* __restrict__ cw,
    const float* __restrict__ cb, float* __restrict__ out)
{
    int idx = blockIdx.x * 256 + threadIdx.x;
    if (idx >= B_SZ * SEQ * CONV_DIM) return;
    int c = idx % CONV_DIM;
    int t = (idx / CONV_DIM) & (SEQ - 1);
    int b = idx / (CONV_DIM * SEQ);

    const float* col = zx + (size_t)b * SEQ * D_IN_PROJ + D_INNER + c;
    float4 w = *(const float4*)(cw + c * 4);
    float acc = cb[c];
    if (t >= 3) acc = fmaf(w.x, col[(size_t)(t - 3) * D_IN_PROJ], acc);
    if (t >= 2) acc = fmaf(w.y, col[(size_t)(t - 2) * D_IN_PROJ], acc);
    if (t >= 1) acc = fmaf(w.z, col[(size_t)(t - 1) * D_IN_PROJ], acc);
    acc = fmaf(w.w, col[(size_t)t * D_IN_PROJ], acc);
    out[idx] = siluf(acc);
}

// -------- dt = softplus(raw+bias); dt and dt*A in [bh][t] layout -----------
__global__ __launch_bounds__(256) void dt2_kernel(
    const float* __restrict__ zx, const float* __restrict__ dt_bias,
    const float* __restrict__ A_log, float* __restrict__ dt_out,
    float* __restrict__ dtA_out)
{
    int idx = blockIdx.x * 256 + threadIdx.x;
    if (idx >= ROWS * NHEADS) return;
    int h = idx & (NHEADS - 1);
    int row = idx >> 3;
    int b = row >> 11;
    int t = row & (SEQ - 1);
    float raw = zx[(size_t)row * D_IN_PROJ + (D_IN_PROJ - NHEADS) + h] + dt_bias[h];
    float dt = (raw > 20.0f) ? raw : log1pf(expf(raw));
    float A = -expf(A_log[h]);
    int o = (b * NHEADS + h) * SEQ + t;
    dt_out[o] = dt;
    dtA_out[o] = dt * A;
}

// ---------------- K_G: G[i][j] = C_i . B_j per (b, chunk) -----------------
__global__ __launch_bounds__(256) void ssd_g_kernel(
    const float* __restrict__ xbc, float* __restrict__ G)
{
    extern __shared__ float sm[];
    float* Cn = sm;                  // [128][68]
    float* Bn = sm + 128 * 68;       // [128][68]

    int c = blockIdx.x, b = blockIdx.y;
    int tid = threadIdx.x;
    int t0 = c * QC;

    for (int q = tid; q < QC * 32; q += 256) {
        int t = q >> 5;
        int n4 = (q & 31) * 4;
        const float* row = xbc + (size_t)(b * SEQ + t0 + t) * CONV_DIM + D_INNER;
        float4 bv = *(const float4*)(row + n4);
        float4 cv = *(const float4*)(row + D_STATE + n4);
        #pragma unroll
        for (int l = 0; l < 4; l++) {
            Bn[(n4 + l) * 68 + t] = (&bv.x)[l];
            Cn[(n4 + l) * 68 + t] = (&cv.x)[l];
        }
    }
    __syncthreads();

    int ty = tid >> 4, tx = tid & 15;
    int i0 = ty * 4, j0 = tx * 4;
    float acc[4][4];
    #pragma unroll
    for (int i = 0; i < 4; i++)
        #pragma unroll
        for (int j = 0; j < 4; j++) acc[i][j] = 0.f;

    #pragma unroll 4
    for (int n = 0; n < D_STATE; n++) {
        float4 cv = *(const float4*)&Cn[n * 68 + i0];
        float4 bv = *(const float4*)&Bn[n * 68 + j0];
        float cf[4] = {cv.x, cv.y, cv.z, cv.w};
        float bf[4] = {bv.x, bv.y, bv.z, bv.w};
        #pragma unroll
        for (int i = 0; i < 4; i++)
            #pragma unroll
            for (int j = 0; j < 4; j++)
                acc[i][j] = fmaf(cf[i], bf[j], acc[i][j]);
    }

    float* Gp = G + (size_t)(b * NCH + c) * QC * QC;
    #pragma unroll
    for (int i = 0; i < 4; i++) {
        float4 v = make_float4(acc[i][0], acc[i][1], acc[i][2], acc[i][3]);
        *(float4*)(Gp + (i0 + i) * QC + j0) = v;
    }
}

// ---------------- K_intra ----------------
__global__ __launch_bounds__(256) void ssd_intra_kernel(
    const float* __restrict__ xbc, const float* __restrict__ dt_t,
    const float* __restrict__ dtA_t, const float* __restrict__ G,
    const float* __restrict__ D_skip,
    float* __restrict__ y_out, float* __restrict__ T_out,
    float* __restrict__ Lam_out)
{
    extern __shared__ float sm[];
    float* Wt = sm;                         // [64][68]
    float* Xj = Wt + QC * 68;               // [64][132]
    float* Bj = Xj + QC * 132;              // [64][132]
    float* s_cs = Bj + QC * 132;            // 64
    float* s_dt = s_cs + QC;                // 64
    float* s_el = s_dt + QC;                // 64

    int c = blockIdx.x, h = blockIdx.y, b = blockIdx.z;
    int tid = threadIdx.x;
    int bh = b * NHEADS + h;
    int t0 = c * QC;

    if (tid < QC) {
        s_cs[tid] = dtA_t[(size_t)bh * SEQ + t0 + tid];
        s_dt[tid] = dt_t[(size_t)bh * SEQ + t0 + tid];
    }
    __syncthreads();
    #pragma unroll
    for (int off = 1; off < QC; off <<= 1) {
        float v = 0.f;
        if (tid < QC && tid >= off) v = s_cs[tid - off];
        __syncthreads();
        if (tid < QC) s_cs[tid] += v;
        __syncthreads();
    }
    if (tid < QC) s_el[tid] = __expf(s_cs[QC - 1] - s_cs[tid]) * s_dt[tid];
    if (tid == 0) Lam_out[bh * NCH + c] = __expf(s_cs[QC - 1]);

    for (int q = tid; q < QC * 32; q += 256) {
        int t = q >> 5;
        int n4 = (q & 31) * 4;
        const float* row = xbc + (size_t)(b * SEQ + t0 + t) * CONV_DIM;
        *(float4*)&Xj[t * 132 + n4] = *(const float4*)(row + h * HEADDIM + n4);
        *(float4*)&Bj[t * 132 + n4] = *(const float4*)(row + D_INNER + n4);
    }

    int ty = tid >> 4, tx = tid & 15;
    {
        int i0 = ty * 4, j0 = tx * 4;
        const float* Gp = G + (size_t)(b * NCH + c) * QC * QC;
        #pragma unroll
        for (int ii = 0; ii < 4; ii++) {
            int i = i0 + ii;
            float4 gv = *(const float4*)(Gp + i * QC + j0);
            float gf[4] = {gv.x, gv.y, gv.z, gv.w};
            #pragma unroll
            for (int jj = 0; jj < 4; jj++) {
                int j = j0 + jj;
                float w = 0.f;
                if (j <= i) w = __expf(s_cs[i] - s_cs[j]) * s_dt[j] * gf[jj];
                Wt[j * 68 + i] = w;
            }
        }
    }
    __syncthreads();

    float Dsk = D_skip[h];

    {
        int i0 = ty * 4, p0 = tx * 8;
        float acc[4][8];
        #pragma unroll
        for (int i = 0; i < 4; i++)
            #pragma unroll
            for (int p = 0; p < 8; p++) acc[i][p] = 0.f;

        int jmax = i0 + 4;
        for (int j = 0; j < jmax; j++) {
            float4 wv = *(const float4*)&Wt[j * 68 + i0];
            float4 xa = *(const float4*)&Xj[j * 132 + p0];
            float4 xb = *(const float4*)&Xj[j * 132 + p0 + 4];
            float wf[4] = {wv.x, wv.y, wv.z, wv.w};
            float xf[8] = {xa.x, xa.y, xa.z, xa.w, xb.x, xb.y, xb.z, xb.w};
            #pragma unroll
            for (int i = 0; i < 4; i++)
                #pragma unroll
                for (int p = 0; p < 8; p++)
                    acc[i][p] = fmaf(wf[i], xf[p], acc[i][p]);
        }
        #pragma unroll
        for (int ii = 0; ii < 4; ii++) {
            int i = i0 + ii;
            size_t row = (size_t)(b * SEQ + t0 + i);
            float* yp = y_out + row * D_INNER + h * HEADDIM + p0;
            float4 x0 = *(const float4*)&Xj[i * 132 + p0];
            float4 x1 = *(const float4*)&Xj[i * 132 + p0 + 4];
            float4 o0 = make_float4(fmaf(Dsk, x0.x, acc[ii][0]),
                                    fmaf(Dsk, x0.y, acc[ii][1]),
                                    fmaf(Dsk, x0.z, acc[ii][2]),
                                    fmaf(Dsk, x0.w, acc[ii][3]));
            float4 o1 = make_float4(fmaf(Dsk, x1.x, acc[ii][4]),
                                    fmaf(Dsk, x1.y, acc[ii][5]),
                                    fmaf(Dsk, x1.z, acc[ii][6]),
                                    fmaf(Dsk, x1.w, acc[ii][7]));
            *(float4*)yp = o0;
            *(float4*)(yp + 4) = o1;
        }
    }

    {
        int p0 = ty * 8, n0 = tx * 8;
        float acc[8][8];
        #pragma unroll
        for (int p = 0; p < 8; p++)
            #pragma unroll
            for (int n = 0; n < 8; n++) acc[p][n] = 0.f;

        #pragma unroll 2
        for (int j = 0; j < QC; j++) {
            float el = s_el[j];
            float4 xa = *(const float4*)&Xj[j * 132 + p0];
            float4 xb = *(const float4*)&Xj[j * 132 + p0 + 4];
            float4 ba = *(const float4*)&Bj[j * 132 + n0];
            float4 bb = *(const float4*)&Bj[j * 132 + n0 + 4];
            float xf[8] = {el * xa.x, el * xa.y, el * xa.z, el * xa.w,
                           el * xb.x, el * xb.y, el * xb.z, el * xb.w};
            float bf[8] = {ba.x, ba.y, ba.z, ba.w, bb.x, bb.y, bb.z, bb.w};
            #pragma unroll
            for (int p = 0; p < 8; p++)
                #pragma unroll
                for (int n = 0; n < 8; n++)
                    acc[p][n] = fmaf(xf[p], bf[n], acc[p][n]);
        }
        float* Tp = T_out + ((size_t)bh * NCH + c) * (HEADDIM * D_STATE);
        #pragma unroll
        for (int pp = 0; pp < 8; pp++) {
            float4 v0 = make_float4(acc[pp][0], acc[pp][1], acc[pp][2], acc[pp][3]);
            float4 v1 = make_float4(acc[pp][4], acc[pp][5], acc[pp][6], acc[pp][7]);
            *(float4*)(Tp + (p0 + pp) * D_STATE + n0) = v0;
            *(float4*)(Tp + (p0 + pp) * D_STATE + n0 + 4) = v1;
        }
    }
}

// ---------------- K_inter: sequential chunk recurrence (float4) ------------
__global__ __launch_bounds__(256) void ssd_inter_kernel(
    const float* __restrict__ T, const float* __restrict__ Lam,
    float* __restrict__ Sp)
{
    int gid = blockIdx.x * 256 + threadIdx.x;   // 0 .. 16*4096-1
    int bh = gid >> 12;
    int pn = gid & 4095;                        // float4 index
    const float4* Tb = (const float4*)(T + ((size_t)bh << 19)) + pn;
    float4* Sb = (float4*)(Sp + ((size_t)bh << 19)) + pn;
    const float* Lb = Lam + bh * NCH;

    float4 S = make_float4(0.f, 0.f, 0.f, 0.f);
    #pragma unroll 4
    for (int c = 0; c < NCH; c++) {
        if (c) Sb[(size_t)c << 12] = S;
        float4 Tv = Tb[(size_t)c << 12];
        float lam = Lb[c];
        S.x = fmaf(lam, S.x, Tv.x);
        S.y = fmaf(lam, S.y, Tv.y);
        S.z = fmaf(lam, S.z, Tv.z);
        S.w = fmaf(lam, S.w, Tv.w);
    }
}

// ---------------- K_out ----------------
__global__ __launch_bounds__(256) void ssd_out_kernel(
    const float* __restrict__ xbc, const float* __restrict__ dtA_t,
    const float* __restrict__ Sp, float* __restrict__ y_out)
{
    int c = blockIdx.x;
    if (c == 0) return;
    extern __shared__ float sm[];
    float* Cn = sm;                       // [128][68]
    float* Spn = Cn + 128 * 68;           // [128][132]
    float* s_cs = Spn + 128 * 132;        // 64

    int h = blockIdx.y, b = blockIdx.z;
    int tid = threadIdx.x;
    int bh = b * NHEADS + h;
    int t0 = c * QC;

    if (tid < QC) s_cs[tid] = dtA_t[(size_t)bh * SEQ + t0 + tid];
    __syncthreads();
    #pragma unroll
    for (int off = 1; off < QC; off <<= 1) {
        float v = 0.f;
        if (tid < QC && tid >= off) v = s_cs[tid - off];
        __syncthreads();
        if (tid < QC) s_cs[tid] += v;
        __syncthreads();
    }

    for (int q = tid; q < QC * 32; q += 256) {
        int t = q >> 5;
        int n4 = (q & 31) * 4;
        const float* row = xbc + (size_t)(b * SEQ + t0 + t) * CONV_DIM
                         + D_INNER + D_STATE;
        float4 v = *(const float4*)(row + n4);
        #pragma unroll
        for (int l = 0; l < 4; l++) Cn[(n4 + l) * 68 + t] = (&v.x)[l];
    }
    const float* Spsrc = Sp + ((size_t)bh * NCH + c) * (HEADDIM * D_STATE);
    for (int q = tid; q < HEADDIM * 32; q += 256) {
        int p = q >> 5;
        int n4 = (q & 31) * 4;
        float4 v = *(const float4*)(Spsrc + p * D_STATE + n4);
        #pragma unroll
        for (int l = 0; l < 4; l++) Spn[(n4 + l) * 132 + p] = (&v.x)[l];
    }
    __syncthreads();

    int ty = tid >> 4, tx = tid & 15;
    int i0 = ty * 4, p0 = tx * 8;
    float acc[4][8];
    #pragma unroll
    for (int i = 0; i < 4; i++)
        #pragma unroll
        for (int p = 0; p < 8; p++) acc[i][p] = 0.f;

    #pragma unroll 2
    for (int n = 0; n < D_STATE; n++) {
        float4 cv = *(const float4*)&Cn[n * 68 + i0];
        float4 sa = *(const float4*)&Spn[n * 132 + p0];
        float4 sb = *(const float4*)&Spn[n * 132 + p0 + 4];
        float cf[4] = {cv.x, cv.y, cv.z, cv.w};
        float sf[8] = {sa.x, sa.y, sa.z, sa.w, sb.x, sb.y, sb.z, sb.w};
        #pragma unroll
        for (int i = 0; i < 4; i++)
            #pragma unroll
            for (int p = 0; p < 8; p++)
                acc[i][p] = fmaf(cf[i], sf[p], acc[i][p]);
    }

    #pragma unroll
    for (int ii = 0; ii < 4; ii++) {
        int i = i0 + ii;
        float e = __expf(s_cs[i]);
        size_t row = (size_t)(b * SEQ + t0 + i);
        float* yp = y_out + row * D_INNER + h * HEADDIM + p0;
        float4 y0 = *(const float4*)yp;
        float4 y1 = *(const float4*)(yp + 4);
        y0.x = fmaf(e, acc[ii][0], y0.x);
        y0.y = fmaf(e, acc[ii][1], y0.y);
        y0.z = fmaf(e, acc[ii][2], y0.z);
        y0.w = fmaf(e, acc[ii][3], y0.w);
        y1.x = fmaf(e, acc[ii][4], y1.x);
        y1.y = fmaf(e, acc[ii][5], y1.y);
        y1.z = fmaf(e, acc[ii][6], y1.z);
        y1.w = fmaf(e, acc[ii][7], y1.w);
        *(float4*)yp = y0;
        *(float4*)(yp + 4) = y1;
    }
}

// ---------------- gate with silu(z), then RMSNorm * gnorm_w ----------------
__global__ __launch_bounds__(256) void gate_kernel(
    const float* __restrict__ y, const float* __restrict__ zx,
    const float* __restrict__ gw, float* __restrict__ out)
{
    int row = blockIdx.x;
    int tid = threadIdx.x;
    int d = tid * 4;
    __shared__ float sm[8];

    float4 y4 = *(const float4*)(y + (size_t)row * D_INNER + d);
    float4 z4 = *(const float4*)(zx + (size_t)row * D_IN_PROJ + d);
    float g0 = y4.x * siluf(z4.x);
    float g1 = y4.y * siluf(z4.y);
    float g2 = y4.z * siluf(z4.z);
    float g3 = y4.w * siluf(z4.w);

    float ss = g0 * g0 + g1 * g1 + g2 * g2 + g3 * g3;
    #pragma unroll
    for (int o = 16; o; o >>= 1) ss += __shfl_xor_sync(0xffffffffu, ss, o);
    if ((tid & 31) == 0) sm[tid >> 5] = ss;
    __syncthreads();
    float tot = 0.f;
    #pragma unroll
    for (int i = 0; i < 8; i++) tot += sm[i];
    float scale = rsqrtf(tot * (1.0f / (float)D_INNER) + EPS);

    float4 w4 = *(const float4*)(gw + d);
    float4 o4 = make_float4(g0 * scale * w4.x, g1 * scale * w4.y,
                            g2 * scale * w4.z, g3 * scale * w4.w);
    *(float4*)(out + (size_t)row * D_INNER + d) = o4;
}

// ---------------- launch ----------------
extern "C" void kernel_launch(void* const* d_in, const int* in_sizes, int n_in,
                              void* d_out, int out_size)
{
    const float* hidden  = (const float*)d_in[0];
    const float* w_in    = (const float*)d_in[1];
    const float* conv_w  = (const float*)d_in[2];
    const float* conv_b  = (const float*)d_in[3];
    const float* dt_bias = (const float*)d_in[4];
    const float* A_log   = (const float*)d_in[5];
    const float* D_skip  = (const float*)d_in[6];
    const float* gnorm_w = (const float*)d_in[7];
    const float* w_out   = (const float*)d_in[8];
    const float* ln1_w   = (const float*)d_in[9];
    const float* ln1_b   = (const float*)d_in[10];
    const float* ln2_w   = (const float*)d_in[11];
    const float* ln2_b   = (const float*)d_in[12];
    const float* mlp_w   = (const float*)d_in[13];
    const float* mlp_b   = (const float*)d_in[14];
    float* outp = (float*)d_out;

    float *h1, *zx, *xbc, *dtT, *dtAT, *Gm, *Tm, *Spm, *Lam, *y, *gg, *res2, *h2;
    cudaGetSymbolAddress((void**)&h1,   g_h1);
    cudaGetSymbolAddress((void**)&zx,   g_zx);
    cudaGetSymbolAddress((void**)&xbc,  g_xbc);
    cudaGetSymbolAddress((void**)&dtT,  g_dtT);
    cudaGetSymbolAddress((void**)&dtAT, g_dtAT);
    cudaGetSymbolAddress((void**)&Gm,   g_G);
    cudaGetSymbolAddress((void**)&Tm,   g_T);
    cudaGetSymbolAddress((void**)&Spm,  g_Sp);
    cudaGetSymbolAddress((void**)&Lam,  g_Lam);
    cudaGetSymbolAddress((void**)&y,    g_y);
    cudaGetSymbolAddress((void**)&gg,   g_g);
    cudaGetSymbolAddress((void**)&res2, g_res2);
    cudaGetSymbolAddress((void**)&h2,   g_h2);

    const int smem_mma   = 12288 * 4;                                // 49152
    const int smem_g     = (128 * 68 * 2) * 4;                       // 69632
    const int smem_intra = (QC * 68 + QC * 132 * 2 + 3 * QC) * 4;    // 85760
    const int smem_out   = (128 * 68 + 128 * 132 + QC) * 4;          // 102656
    cudaFuncSetAttribute(gemm_mma<false, false>,
        cudaFuncAttributeMaxDynamicSharedMemorySize, smem_mma);
    cudaFuncSetAttribute(gemm_mma<true, false>,
        cudaFuncAttributeMaxDynamicSharedMemorySize, smem_mma);
    cudaFuncSetAttribute(gemm_mma<false, true>,
        cudaFuncAttributeMaxDynamicSharedMemorySize, smem_mma);
    cudaFuncSetAttribute(ssd_g_kernel,
        cudaFuncAttributeMaxDynamicSharedMemorySize, smem_g);
    cudaFuncSetAttribute(ssd_intra_kernel,
        cudaFuncAttributeMaxDynamicSharedMemorySize, smem_intra);
    cudaFuncSetAttribute(ssd_out_kernel,
        cudaFuncAttributeMaxDynamicSharedMemorySize, smem_out);

    // 1) ln1
    ln_kernel<<<ROWS, 128>>>(hidden, ln1_w, ln1_b, h1);

    // 2) in_proj (tensor cores)
    {
        dim3 grid((D_IN_PROJ + 63) / 64, ROWS / 128);
        gemm_mma<false, false><<<grid, 256, smem_mma>>>(
            h1, D_MODEL, w_in, D_MODEL, zx, D_IN_PROJ, D_IN_PROJ, D_MODEL,
            nullptr, nullptr);
    }

    // 3) conv + silu
    {
        int total = B_SZ * SEQ * CONV_DIM;
        conv_kernel<<<(total + 255) / 256, 256>>>(zx, conv_w, conv_b, xbc);
    }

    // 4) dt / dtA
    dt2_kernel<<<(ROWS * NHEADS + 255) / 256, 256>>>(zx, dt_bias, A_log, dtT, dtAT);

    // 5) chunked SSD
    {
        dim3 gg_(NCH, B_SZ);
        ssd_g_kernel<<<gg_, 256, smem_g>>>(xbc, Gm);

        dim3 gi(NCH, NHEADS, B_SZ);
        ssd_intra_kernel<<<gi, 256, smem_intra>>>(xbc, dtT, dtAT, Gm, D_skip,
                                                  y, Tm, Lam);

        ssd_inter_kernel<<<(NBH * HEADDIM * D_STATE / 4) / 256, 256>>>(Tm, Lam, Spm);

        ssd_out_kernel<<<gi, 256, smem_out>>>(xbc, dtAT, Spm, y);
    }

    // 6) gate + rmsnorm
    gate_kernel<<<ROWS, 256>>>(y, zx, gnorm_w, gg);

    // 7) out_proj + residual (tensor cores)
    {
        dim3 grid((D_MODEL + 63) / 64, ROWS / 128);
        gemm_mma<true, false><<<grid, 256, smem_mma>>>(
            gg, D_INNER, w_out, D_INNER, res2, D_MODEL, D_MODEL, D_INNER,
            hidden, nullptr);
    }

    // 8) ln2
    ln_kernel<<<ROWS, 128>>>(res2, ln2_w, ln2_b, h2);

    // 9) mlp (tensor cores)
    {
        dim3 grid((D_MODEL + 63) / 64, ROWS / 128);
        gemm_mma<false, true><<<grid, 256, smem_mma>>>(
            h2, D_MODEL, mlp_w, D_MODEL, outp, D_MODEL, D_MODEL, D_MODEL,
            nullptr, mlp_b);
    }
    (void)in_sizes; (void)n_in; (void)out_size;
}

// round 5
// speedup vs baseline: 1.0635x; 1.0635x over previous
#include <cuda_runtime.h>
#include <cuda_bf16.h>
#include <cstdint>

#define B_SZ 2
#define SEQ 2048
#define ROWS (B_SZ * SEQ)          // 4096
#define D_MODEL 128
#define D_INNER 1024
#define NHEADS 8
#define HEADDIM 128
#define D_STATE 128
#define D_CONV 4
#define CONV_DIM (D_INNER + 2 * D_STATE)   // 1280
#define D_IN_PROJ (2 * D_INNER + 2 * D_STATE + NHEADS)  // 2312
#define EPS 1e-5f

#define QC 64
#define NCH (SEQ / QC)             // 32
#define NBH (B_SZ * NHEADS)        // 16

// padded N for w_in fragments: 37 blocks * 64 = 2368
#define WIN_NPAD 2368

// ---------------- scratch (no allocations allowed) ----------------
__device__ float g_zx[ROWS * D_IN_PROJ];
__device__ float g_xbc[ROWS * CONV_DIM];
__device__ float g_dtT[NBH * SEQ];
__device__ float g_dtAT[NBH * SEQ];
__device__ float g_G[B_SZ * NCH * QC * QC];
__device__ float g_T[NBH * NCH * HEADDIM * D_STATE];
__device__ float g_Sp[NBH * NCH * HEADDIM * D_STATE];
__device__ float g_Lam[NBH * NCH];
__device__ float g_y[ROWS * D_INNER];
__device__ float g_res2[ROWS * D_MODEL];

// fragment-order buffers (hi/lo tf32)
__device__ float g_h1fh[ROWS * D_MODEL];                // A frags, KS=16
__device__ float g_h1fl[ROWS * D_MODEL];
__device__ float g_ggfh[ROWS * D_INNER];                // A frags, KS=128
__device__ float g_ggfl[ROWS * D_INNER];
__device__ float g_h2fh[ROWS * D_MODEL];
__device__ float g_h2fl[ROWS * D_MODEL];
__device__ float g_winfh[WIN_NPAD * D_MODEL];           // B frags
__device__ float g_winfl[WIN_NPAD * D_MODEL];
__device__ float g_woutfh[D_MODEL * D_INNER];
__device__ float g_woutfl[D_MODEL * D_INNER];
__device__ float g_wmlpfh[D_MODEL * D_MODEL];
__device__ float g_wmlpfl[D_MODEL * D_MODEL];

__device__ __forceinline__ float siluf(float v) {
    return v / (1.0f + expf(-v));
}

// ---------------- tf32 helpers ----------------
__device__ __forceinline__ void tf32_split(float f, float& hi, float& lo) {
    uint32_t h;
    asm("cvt.rna.tf32.f32 %0, %1;" : "=r"(h) : "f"(f));
    float hf = __uint_as_float(h);
    float r = f - hf;
    uint32_t l;
    asm("cvt.rna.tf32.f32 %0, %1;" : "=r"(l) : "f"(r));
    hi = hf;
    lo = __uint_as_float(l);
}

__device__ __forceinline__ void mma_tf32(float* d,
    uint32_t a0, uint32_t a1, uint32_t a2, uint32_t a3,
    uint32_t b0, uint32_t b1)
{
    asm volatile(
        "mma.sync.aligned.m16n8k8.row.col.f32.tf32.tf32.f32 "
        "{%0,%1,%2,%3},{%4,%5,%6,%7},{%8,%9},{%0,%1,%2,%3};"
        : "+f"(d[0]), "+f"(d[1]), "+f"(d[2]), "+f"(d[3])
        : "r"(a0), "r"(a1), "r"(a2), "r"(a3), "r"(b0), "r"(b1));
}

// A-frag index for element (m, k), K-step count KS
__device__ __forceinline__ int afrag_idx(int m, int k, int KS) {
    int mt = m >> 4, r = m & 15;
    int ks = k >> 3, c = k & 7;
    int ln = ((r & 7) << 2) | (c & 3);
    int reg = ((r >> 3) & 1) | (((c >> 2) & 1) << 1);
    return ((mt * KS + ks) * 32 + ln) * 4 + reg;
}

// ---------------- LayerNorm -> A-fragment (hi/lo), K=128 ----------------
__global__ __launch_bounds__(128) void ln_frag_kernel(
    const float* __restrict__ x, const float* __restrict__ w,
    const float* __restrict__ b, float* __restrict__ Ah,
    float* __restrict__ Al)
{
    int row = blockIdx.x;
    int tid = threadIdx.x;
    __shared__ float sm[4];
    float v = x[(size_t)row * D_MODEL + tid];

    float s = v;
    #pragma unroll
    for (int o = 16; o; o >>= 1) s += __shfl_xor_sync(0xffffffffu, s, o);
    if ((tid & 31) == 0) sm[tid >> 5] = s;
    __syncthreads();
    float mean = (sm[0] + sm[1] + sm[2] + sm[3]) * (1.0f / 128.0f);
    __syncthreads();

    float d = v - mean;
    float q = d * d;
    #pragma unroll
    for (int o = 16; o; o >>= 1) q += __shfl_xor_sync(0xffffffffu, q, o);
    if ((tid & 31) == 0) sm[tid >> 5] = q;
    __syncthreads();
    float var = (sm[0] + sm[1] + sm[2] + sm[3]) * (1.0f / 128.0f);

    float o = d * rsqrtf(var + EPS) * w[tid] + b[tid];
    float hi, lo;
    tf32_split(o, hi, lo);
    int idx = afrag_idx(row, tid, 16);
    Ah[idx] = hi;
    Al[idx] = lo;
}

// ---------------- W -> B-fragment (hi/lo), zero-padded to Npad -------------
__global__ __launch_bounds__(256) void wsplit_kernel(
    const float* __restrict__ W, int N, int Npad, int K,
    float* __restrict__ Bh, float* __restrict__ Bl)
{
    int idx = blockIdx.x * 256 + threadIdx.x;
    if (idx >= Npad * K) return;
    int n = idx / K, k = idx - n * K;
    float v = (n < N) ? W[(size_t)n * K + k] : 0.f;
    int nt = n >> 3, gg = n & 7;
    int ks = k >> 3, c = k & 7;
    int ln = (gg << 2) | (c & 3);
    int reg = (c >> 2) & 1;
    int KS = K >> 3;
    int o = ((nt * KS + ks) * 32 + ln) * 2 + reg;
    float hi, lo;
    tf32_split(v, hi, lo);
    Bh[o] = hi;
    Bl[o] = lo;
}

// ---------------- fragment GEMM: C = A[M,K] @ W[N,K]^T (3x tf32) -----------
// block tile 128x64, 8 warps (4x2), warp tile 32x32. No smem, no syncs.
template<bool RESID, bool BIAS>
__global__ __launch_bounds__(256) void gemm_frag(
    const float4* __restrict__ Ah, const float4* __restrict__ Al,
    const float2* __restrict__ Bh, const float2* __restrict__ Bl,
    float* __restrict__ C, int ldc, int N, int K,
    const float* __restrict__ resid, const float* __restrict__ bias)
{
    const int lane = threadIdx.x & 31;
    const int warp = threadIdx.x >> 5;
    const int wm = warp >> 1, wn = warp & 1;
    const int KS = K >> 3;
    const int mt0 = blockIdx.y * 8 + wm * 2;
    const int nt0 = blockIdx.x * 8 + wn * 4;

    const float4* pAh0 = Ah + (size_t)mt0 * KS * 32 + lane;
    const float4* pAh1 = pAh0 + (size_t)KS * 32;
    const float4* pAl0 = Al + (size_t)mt0 * KS * 32 + lane;
    const float4* pAl1 = pAl0 + (size_t)KS * 32;
    const float2* pBh = Bh + (size_t)nt0 * KS * 32 + lane;
    const float2* pBl = Bl + (size_t)nt0 * KS * 32 + lane;

    float acc[2][4][4];
    #pragma unroll
    for (int mi = 0; mi < 2; mi++)
        #pragma unroll
        for (int ni = 0; ni < 4; ni++)
            #pragma unroll
            for (int r = 0; r < 4; r++) acc[mi][ni][r] = 0.f;

    #pragma unroll 2
    for (int ks = 0; ks < KS; ks++) {
        float4 ah[2], al[2];
        ah[0] = pAh0[(size_t)ks * 32];
        ah[1] = pAh1[(size_t)ks * 32];
        al[0] = pAl0[(size_t)ks * 32];
        al[1] = pAl1[(size_t)ks * 32];
        float2 bh[4], bl[4];
        #pragma unroll
        for (int ni = 0; ni < 4; ni++) {
            size_t o = (size_t)ni * KS * 32 + (size_t)ks * 32;
            bh[ni] = pBh[o];
            bl[ni] = pBl[o];
        }
        #pragma unroll
        for (int mi = 0; mi < 2; mi++) {
            uint32_t a0 = __float_as_uint(ah[mi].x);
            uint32_t a1 = __float_as_uint(ah[mi].y);
            uint32_t a2 = __float_as_uint(ah[mi].z);
            uint32_t a3 = __float_as_uint(ah[mi].w);
            uint32_t l0 = __float_as_uint(al[mi].x);
            uint32_t l1 = __float_as_uint(al[mi].y);
            uint32_t l2 = __float_as_uint(al[mi].z);
            uint32_t l3 = __float_as_uint(al[mi].w);
            #pragma unroll
            for (int ni = 0; ni < 4; ni++) {
                uint32_t b0 = __float_as_uint(bh[ni].x);
                uint32_t b1 = __float_as_uint(bh[ni].y);
                uint32_t c0 = __float_as_uint(bl[ni].x);
                uint32_t c1 = __float_as_uint(bl[ni].y);
                mma_tf32(acc[mi][ni], a0, a1, a2, a3, b0, b1);
                mma_tf32(acc[mi][ni], a0, a1, a2, a3, c0, c1);
                mma_tf32(acc[mi][ni], l0, l1, l2, l3, b0, b1);
            }
        }
    }

    const int g = lane >> 2;
    const int tq = lane & 3;
    #pragma unroll
    for (int mi = 0; mi < 2; mi++) {
        #pragma unroll
        for (int ni = 0; ni < 4; ni++) {
            int row = (mt0 + mi) * 16 + g;
            int col = (nt0 + ni) * 8 + tq * 2;
            if (col < N) {
                float2 v0 = make_float2(acc[mi][ni][0], acc[mi][ni][1]);
                float2 v1 = make_float2(acc[mi][ni][2], acc[mi][ni][3]);
                if (RESID) {
                    float2 r0 = *(const float2*)(resid + (size_t)row * ldc + col);
                    float2 r1 = *(const float2*)(resid + (size_t)(row + 8) * ldc + col);
                    v0.x += r0.x; v0.y += r0.y;
                    v1.x += r1.x; v1.y += r1.y;
                }
                if (BIAS) {
                    float2 bb = *(const float2*)(bias + col);
                    v0.x += bb.x; v0.y += bb.y;
                    v1.x += bb.x; v1.y += bb.y;
                }
                *(float2*)(C + (size_t)row * ldc + col) = v0;
                *(float2*)(C + (size_t)(row + 8) * ldc + col) = v1;
            }
        }
    }
}

// ---------------- depthwise causal conv (k=4) + bias + silu ----------------
__global__ __launch_bounds__(256) void conv_kernel(
    const float* __restrict__ zx, const float* __restrict__ cw,
    const float* __restrict__ cb, float* __restrict__ out)
{
    int idx = blockIdx.x * 256 + threadIdx.x;
    if (idx >= B_SZ * SEQ * CONV_DIM) return;
    int c = idx % CONV_DIM;
    int t = (idx / CONV_DIM) & (SEQ - 1);
    int b = idx / (CONV_DIM * SEQ);

    const float* col = zx + (size_t)b * SEQ * D_IN_PROJ + D_INNER + c;
    float4 w = *(const float4*)(cw + c * 4);
    float acc = cb[c];
    if (t >= 3) acc = fmaf(w.x, col[(size_t)(t - 3) * D_IN_PROJ], acc);
    if (t >= 2) acc = fmaf(w.y, col[(size_t)(t - 2) * D_IN_PROJ], acc);
    if (t >= 1) acc = fmaf(w.z, col[(size_t)(t - 1) * D_IN_PROJ], acc);
    acc = fmaf(w.w, col[(size_t)t * D_IN_PROJ], acc);
    out[idx] = siluf(acc);
}

// -------- dt = softplus(raw+bias); dt and dt*A in [bh][t] layout -----------
__global__ __launch_bounds__(256) void dt2_kernel(
    const float* __restrict__ zx, const float* __restrict__ dt_bias,
    const float* __restrict__ A_log, float* __restrict__ dt_out,
    float* __restrict__ dtA_out)
{
    int idx = blockIdx.x * 256 + threadIdx.x;
    if (idx >= ROWS * NHEADS) return;
    int h = idx & (NHEADS - 1);
    int row = idx >> 3;
    int b = row >> 11;
    int t = row & (SEQ - 1);
    float raw = zx[(size_t)row * D_IN_PROJ + (D_IN_PROJ - NHEADS) + h] + dt_bias[h];
    float dt = (raw > 20.0f) ? raw : log1pf(expf(raw));
    float A = -expf(A_log[h]);
    int o = (b * NHEADS + h) * SEQ + t;
    dt_out[o] = dt;
    dtA_out[o] = dt * A;
}

// ---------------- K_G: G[i][j] = C_i . B_j per (b, chunk) -----------------
__global__ __launch_bounds__(256) void ssd_g_kernel(
    const float* __restrict__ xbc, float* __restrict__ G)
{
    extern __shared__ float sm[];
    float* Cn = sm;                  // [128][68]
    float* Bn = sm + 128 * 68;       // [128][68]

    int c = blockIdx.x, b = blockIdx.y;
    int tid = threadIdx.x;
    int t0 = c * QC;

    for (int q = tid; q < QC * 32; q += 256) {
        int t = q >> 5;
        int n4 = (q & 31) * 4;
        const float* row = xbc + (size_t)(b * SEQ + t0 + t) * CONV_DIM + D_INNER;
        float4 bv = *(const float4*)(row + n4);
        float4 cv = *(const float4*)(row + D_STATE + n4);
        #pragma unroll
        for (int l = 0; l < 4; l++) {
            Bn[(n4 + l) * 68 + t] = (&bv.x)[l];
            Cn[(n4 + l) * 68 + t] = (&cv.x)[l];
        }
    }
    __syncthreads();

    int ty = tid >> 4, tx = tid & 15;
    int i0 = ty * 4, j0 = tx * 4;
    float acc[4][4];
    #pragma unroll
    for (int i = 0; i < 4; i++)
        #pragma unroll
        for (int j = 0; j < 4; j++) acc[i][j] = 0.f;

    #pragma unroll 4
    for (int n = 0; n < D_STATE; n++) {
        float4 cv = *(const float4*)&Cn[n * 68 + i0];
        float4 bv = *(const float4*)&Bn[n * 68 + j0];
        float cf[4] = {cv.x, cv.y, cv.z, cv.w};
        float bf[4] = {bv.x, bv.y, bv.z, bv.w};
        #pragma unroll
        for (int i = 0; i < 4; i++)
            #pragma unroll
            for (int j = 0; j < 4; j++)
                acc[i][j] = fmaf(cf[i], bf[j], acc[i][j]);
    }

    float* Gp = G + (size_t)(b * NCH + c) * QC * QC;
    #pragma unroll
    for (int i = 0; i < 4; i++) {
        float4 v = make_float4(acc[i][0], acc[i][1], acc[i][2], acc[i][3]);
        *(float4*)(Gp + (i0 + i) * QC + j0) = v;
    }
}

// ---------------- K_intra ----------------
__global__ __launch_bounds__(256) void ssd_intra_kernel(
    const float* __restrict__ xbc, const float* __restrict__ dt_t,
    const float* __restrict__ dtA_t, const float* __restrict__ G,
    const float* __restrict__ D_skip,
    float* __restrict__ y_out, float* __restrict__ T_out,
    float* __restrict__ Lam_out)
{
    extern __shared__ float sm[];
    float* Wt = sm;                         // [64][68]
    float* Xj = Wt + QC * 68;               // [64][132]
    float* Bj = Xj + QC * 132;              // [64][132]
    float* s_cs = Bj + QC * 132;            // 64
    float* s_dt = s_cs + QC;                // 64
    float* s_el = s_dt + QC;                // 64

    int c = blockIdx.x, h = blockIdx.y, b = blockIdx.z;
    int tid = threadIdx.x;
    int bh = b * NHEADS + h;
    int t0 = c * QC;

    if (tid < QC) {
        s_cs[tid] = dtA_t[(size_t)bh * SEQ + t0 + tid];
        s_dt[tid] = dt_t[(size_t)bh * SEQ + t0 + tid];
    }
    __syncthreads();
    #pragma unroll
    for (int off = 1; off < QC; off <<= 1) {
        float v = 0.f;
        if (tid < QC && tid >= off) v = s_cs[tid - off];
        __syncthreads();
        if (tid < QC) s_cs[tid] += v;
        __syncthreads();
    }
    if (tid < QC) s_el[tid] = __expf(s_cs[QC - 1] - s_cs[tid]) * s_dt[tid];
    if (tid == 0) Lam_out[bh * NCH + c] = __expf(s_cs[QC - 1]);

    for (int q = tid; q < QC * 32; q += 256) {
        int t = q >> 5;
        int n4 = (q & 31) * 4;
        const float* row = xbc + (size_t)(b * SEQ + t0 + t) * CONV_DIM;
        *(float4*)&Xj[t * 132 + n4] = *(const float4*)(row + h * HEADDIM + n4);
        *(float4*)&Bj[t * 132 + n4] = *(const float4*)(row + D_INNER + n4);
    }

    int ty = tid >> 4, tx = tid & 15;
    {
        int i0 = ty * 4, j0 = tx * 4;
        const float* Gp = G + (size_t)(b * NCH + c) * QC * QC;
        #pragma unroll
        for (int ii = 0; ii < 4; ii++) {
            int i = i0 + ii;
            float4 gv = *(const float4*)(Gp + i * QC + j0);
            float gf[4] = {gv.x, gv.y, gv.z, gv.w};
            #pragma unroll
            for (int jj = 0; jj < 4; jj++) {
                int j = j0 + jj;
                float w = 0.f;
                if (j <= i) w = __expf(s_cs[i] - s_cs[j]) * s_dt[j] * gf[jj];
                Wt[j * 68 + i] = w;
            }
        }
    }
    __syncthreads();

    float Dsk = D_skip[h];

    {
        int i0 = ty * 4, p0 = tx * 8;
        float acc[4][8];
        #pragma unroll
        for (int i = 0; i < 4; i++)
            #pragma unroll
            for (int p = 0; p < 8; p++) acc[i][p] = 0.f;

        int jmax = i0 + 4;
        for (int j = 0; j < jmax; j++) {
            float4 wv = *(const float4*)&Wt[j * 68 + i0];
            float4 xa = *(const float4*)&Xj[j * 132 + p0];
            float4 xb = *(const float4*)&Xj[j * 132 + p0 + 4];
            float wf[4] = {wv.x, wv.y, wv.z, wv.w};
            float xf[8] = {xa.x, xa.y, xa.z, xa.w, xb.x, xb.y, xb.z, xb.w};
            #pragma unroll
            for (int i = 0; i < 4; i++)
                #pragma unroll
                for (int p = 0; p < 8; p++)
                    acc[i][p] = fmaf(wf[i], xf[p], acc[i][p]);
        }
        #pragma unroll
        for (int ii = 0; ii < 4; ii++) {
            int i = i0 + ii;
            size_t row = (size_t)(b * SEQ + t0 + i);
            float* yp = y_out + row * D_INNER + h * HEADDIM + p0;
            float4 x0 = *(const float4*)&Xj[i * 132 + p0];
            float4 x1 = *(const float4*)&Xj[i * 132 + p0 + 4];
            float4 o0 = make_float4(fmaf(Dsk, x0.x, acc[ii][0]),
                                    fmaf(Dsk, x0.y, acc[ii][1]),
                                    fmaf(Dsk, x0.z, acc[ii][2]),
                                    fmaf(Dsk, x0.w, acc[ii][3]));
            float4 o1 = make_float4(fmaf(Dsk, x1.x, acc[ii][4]),
                                    fmaf(Dsk, x1.y, acc[ii][5]),
                                    fmaf(Dsk, x1.z, acc[ii][6]),
                                    fmaf(Dsk, x1.w, acc[ii][7]));
            *(float4*)yp = o0;
            *(float4*)(yp + 4) = o1;
        }
    }

    {
        int p0 = ty * 8, n0 = tx * 8;
        float acc[8][8];
        #pragma unroll
        for (int p = 0; p < 8; p++)
            #pragma unroll
            for (int n = 0; n < 8; n++) acc[p][n] = 0.f;

        #pragma unroll 2
        for (int j = 0; j < QC; j++) {
            float el = s_el[j];
            float4 xa = *(const float4*)&Xj[j * 132 + p0];
            float4 xb = *(const float4*)&Xj[j * 132 + p0 + 4];
            float4 ba = *(const float4*)&Bj[j * 132 + n0];
            float4 bb = *(const float4*)&Bj[j * 132 + n0 + 4];
            float xf[8] = {el * xa.x, el * xa.y, el * xa.z, el * xa.w,
                           el * xb.x, el * xb.y, el * xb.z, el * xb.w};
            float bf[8] = {ba.x, ba.y, ba.z, ba.w, bb.x, bb.y, bb.z, bb.w};
            #pragma unroll
            for (int p = 0; p < 8; p++)
                #pragma unroll
                for (int n = 0; n < 8; n++)
                    acc[p][n] = fmaf(xf[p], bf[n], acc[p][n]);
        }
        float* Tp = T_out + ((size_t)bh * NCH + c) * (HEADDIM * D_STATE);
        #pragma unroll
        for (int pp = 0; pp < 8; pp++) {
            float4 v0 = make_float4(acc[pp][0], acc[pp][1], acc[pp][2], acc[pp][3]);
            float4 v1 = make_float4(acc[pp][4], acc[pp][5], acc[pp][6], acc[pp][7]);
            *(float4*)(Tp + (p0 + pp) * D_STATE + n0) = v0;
            *(float4*)(Tp + (p0 + pp) * D_STATE + n0 + 4) = v1;
        }
    }
}

// ---------------- K_inter ----------------
__global__ __launch_bounds__(256) void ssd_inter_kernel(
    const float* __restrict__ T, const float* __restrict__ Lam,
    float* __restrict__ Sp)
{
    int gid = blockIdx.x * 256 + threadIdx.x;
    int bh = gid >> 12;
    int pn = gid & 4095;
    const float4* Tb = (const float4*)(T + ((size_t)bh << 19)) + pn;
    float4* Sb = (float4*)(Sp + ((size_t)bh << 19)) + pn;
    const float* Lb = Lam + bh * NCH;

    float4 S = make_float4(0.f, 0.f, 0.f, 0.f);
    #pragma unroll 4
    for (int c = 0; c < NCH; c++) {
        if (c) Sb[(size_t)c << 12] = S;
        float4 Tv = Tb[(size_t)c << 12];
        float lam = Lb[c];
        S.x = fmaf(lam, S.x, Tv.x);
        S.y = fmaf(lam, S.y, Tv.y);
        S.z = fmaf(lam, S.z, Tv.z);
        S.w = fmaf(lam, S.w, Tv.w);
    }
}

// ---------------- K_out ----------------
__global__ __launch_bounds__(256) void ssd_out_kernel(
    const float* __restrict__ xbc, const float* __restrict__ dtA_t,
    const float* __restrict__ Sp, float* __restrict__ y_out)
{
    int c = blockIdx.x;
    if (c == 0) return;
    extern __shared__ float sm[];
    float* Cn = sm;                       // [128][68]
    float* Spn = Cn + 128 * 68;           // [128][132]
    float* s_cs = Spn + 128 * 132;        // 64

    int h = blockIdx.y, b = blockIdx.z;
    int tid = threadIdx.x;
    int bh = b * NHEADS + h;
    int t0 = c * QC;

    if (tid < QC) s_cs[tid] = dtA_t[(size_t)bh * SEQ + t0 + tid];
    __syncthreads();
    #pragma unroll
    for (int off = 1; off < QC; off <<= 1) {
        float v = 0.f;
        if (tid < QC && tid >= off) v = s_cs[tid - off];
        __syncthreads();
        if (tid < QC) s_cs[tid] += v;
        __syncthreads();
    }

    for (int q = tid; q < QC * 32; q += 256) {
        int t = q >> 5;
        int n4 = (q & 31) * 4;
        const float* row = xbc + (size_t)(b * SEQ + t0 + t) * CONV_DIM
                         + D_INNER + D_STATE;
        float4 v = *(const float4*)(row + n4);
        #pragma unroll
        for (int l = 0; l < 4; l++) Cn[(n4 + l) * 68 + t] = (&v.x)[l];
    }
    const float* Spsrc = Sp + ((size_t)bh * NCH + c) * (HEADDIM * D_STATE);
    for (int q = tid; q < HEADDIM * 32; q += 256) {
        int p = q >> 5;
        int n4 = (q & 31) * 4;
        float4 v = *(const float4*)(Spsrc + p * D_STATE + n4);
        #pragma unroll
        for (int l = 0; l < 4; l++) Spn[(n4 + l) * 132 + p] = (&v.x)[l];
    }
    __syncthreads();

    int ty = tid >> 4, tx = tid & 15;
    int i0 = ty * 4, p0 = tx * 8;
    float acc[4][8];
    #pragma unroll
    for (int i = 0; i < 4; i++)
        #pragma unroll
        for (int p = 0; p < 8; p++) acc[i][p] = 0.f;

    #pragma unroll 2
    for (int n = 0; n < D_STATE; n++) {
        float4 cv = *(const float4*)&Cn[n * 68 + i0];
        float4 sa = *(const float4*)&Spn[n * 132 + p0];
        float4 sb = *(const float4*)&Spn[n * 132 + p0 + 4];
        float cf[4] = {cv.x, cv.y, cv.z, cv.w};
        float sf[8] = {sa.x, sa.y, sa.z, sa.w, sb.x, sb.y, sb.z, sb.w};
        #pragma unroll
        for (int i = 0; i < 4; i++)
            #pragma unroll
            for (int p = 0; p < 8; p++)
                acc[i][p] = fmaf(cf[i], sf[p], acc[i][p]);
    }

    #pragma unroll
    for (int ii = 0; ii < 4; ii++) {
        int i = i0 + ii;
        float e = __expf(s_cs[i]);
        size_t row = (size_t)(b * SEQ + t0 + i);
        float* yp = y_out + row * D_INNER + h * HEADDIM + p0;
        float4 y0 = *(const float4*)yp;
        float4 y1 = *(const float4*)(yp + 4);
        y0.x = fmaf(e, acc[ii][0], y0.x);
        y0.y = fmaf(e, acc[ii][1], y0.y);
        y0.z = fmaf(e, acc[ii][2], y0.z);
        y0.w = fmaf(e, acc[ii][3], y0.w);
        y1.x = fmaf(e, acc[ii][4], y1.x);
        y1.y = fmaf(e, acc[ii][5], y1.y);
        y1.z = fmaf(e, acc[ii][6], y1.z);
        y1.w = fmaf(e, acc[ii][7], y1.w);
        *(float4*)yp = y0;
        *(float4*)(yp + 4) = y1;
    }
}

// ------- gate + RMSNorm -> A-fragment (hi/lo) output, K=1024 (KS=128) ------
__global__ __launch_bounds__(256) void gate_frag_kernel(
    const float* __restrict__ y, const float* __restrict__ zx,
    const float* __restrict__ gw, float* __restrict__ Ah,
    float* __restrict__ Al)
{
    int row = blockIdx.x;
    int tid = threadIdx.x;
    int d = tid * 4;
    __shared__ float sm[8];

    float4 y4 = *(const float4*)(y + (size_t)row * D_INNER + d);
    float4 z4 = *(const float4*)(zx + (size_t)row * D_IN_PROJ + d);
    float g0 = y4.x * siluf(z4.x);
    float g1 = y4.y * siluf(z4.y);
    float g2 = y4.z * siluf(z4.z);
    float g3 = y4.w * siluf(z4.w);

    float ss = g0 * g0 + g1 * g1 + g2 * g2 + g3 * g3;
    #pragma unroll
    for (int o = 16; o; o >>= 1) ss += __shfl_xor_sync(0xffffffffu, ss, o);
    if ((tid & 31) == 0) sm[tid >> 5] = ss;
    __syncthreads();
    float tot = 0.f;
    #pragma unroll
    for (int i = 0; i < 8; i++) tot += sm[i];
    float scale = rsqrtf(tot * (1.0f / (float)D_INNER) + EPS);

    float4 w4 = *(const float4*)(gw + d);
    float vals[4] = {g0 * scale * w4.x, g1 * scale * w4.y,
                     g2 * scale * w4.z, g3 * scale * w4.w};

    // fragment scatter: KS=128
    int mt = row >> 4, r = row & 15;
    int ks = d >> 3;
    int reg = ((r >> 3) & 1) | (((d >> 2) & 1) << 1);
    int lnb = (r & 7) << 2;
    int base = ((mt * 128 + ks) * 32 + lnb) * 4 + reg;
    #pragma unroll
    for (int l = 0; l < 4; l++) {
        float hi, lo;
        tf32_split(vals[l], hi, lo);
        Ah[base + l * 4] = hi;
        Al[base + l * 4] = lo;
    }
}

// ---------------- launch ----------------
extern "C" void kernel_launch(void* const* d_in, const int* in_sizes, int n_in,
                              void* d_out, int out_size)
{
    const float* hidden  = (const float*)d_in[0];
    const float* w_in    = (const float*)d_in[1];
    const float* conv_w  = (const float*)d_in[2];
    const float* conv_b  = (const float*)d_in[3];
    const float* dt_bias = (const float*)d_in[4];
    const float* A_log   = (const float*)d_in[5];
    const float* D_skip  = (const float*)d_in[6];
    const float* gnorm_w = (const float*)d_in[7];
    const float* w_out   = (const float*)d_in[8];
    const float* ln1_w   = (const float*)d_in[9];
    const float* ln1_b   = (const float*)d_in[10];
    const float* ln2_w   = (const float*)d_in[11];
    const float* ln2_b   = (const float*)d_in[12];
    const float* mlp_w   = (const float*)d_in[13];
    const float* mlp_b   = (const float*)d_in[14];
    float* outp = (float*)d_out;

    float *zx, *xbc, *dtT, *dtAT, *Gm, *Tm, *Spm, *Lam, *y, *res2;
    float *h1fh, *h1fl, *ggfh, *ggfl, *h2fh, *h2fl;
    float *winfh, *winfl, *woutfh, *woutfl, *wmlpfh, *wmlpfl;
    cudaGetSymbolAddress((void**)&zx,   g_zx);
    cudaGetSymbolAddress((void**)&xbc,  g_xbc);
    cudaGetSymbolAddress((void**)&dtT,  g_dtT);
    cudaGetSymbolAddress((void**)&dtAT, g_dtAT);
    cudaGetSymbolAddress((void**)&Gm,   g_G);
    cudaGetSymbolAddress((void**)&Tm,   g_T);
    cudaGetSymbolAddress((void**)&Spm,  g_Sp);
    cudaGetSymbolAddress((void**)&Lam,  g_Lam);
    cudaGetSymbolAddress((void**)&y,    g_y);
    cudaGetSymbolAddress((void**)&res2, g_res2);
    cudaGetSymbolAddress((void**)&h1fh, g_h1fh);
    cudaGetSymbolAddress((void**)&h1fl, g_h1fl);
    cudaGetSymbolAddress((void**)&ggfh, g_ggfh);
    cudaGetSymbolAddress((void**)&ggfl, g_ggfl);
    cudaGetSymbolAddress((void**)&h2fh, g_h2fh);
    cudaGetSymbolAddress((void**)&h2fl, g_h2fl);
    cudaGetSymbolAddress((void**)&winfh,  g_winfh);
    cudaGetSymbolAddress((void**)&winfl,  g_winfl);
    cudaGetSymbolAddress((void**)&woutfh, g_woutfh);
    cudaGetSymbolAddress((void**)&woutfl, g_woutfl);
    cudaGetSymbolAddress((void**)&wmlpfh, g_wmlpfh);
    cudaGetSymbolAddress((void**)&wmlpfl, g_wmlpfl);

    const int smem_g     = (128 * 68 * 2) * 4;
    const int smem_intra = (QC * 68 + QC * 132 * 2 + 3 * QC) * 4;
    const int smem_out   = (128 * 68 + 128 * 132 + QC) * 4;
    cudaFuncSetAttribute(ssd_g_kernel,
        cudaFuncAttributeMaxDynamicSharedMemorySize, smem_g);
    cudaFuncSetAttribute(ssd_intra_kernel,
        cudaFuncAttributeMaxDynamicSharedMemorySize, smem_intra);
    cudaFuncSetAttribute(ssd_out_kernel,
        cudaFuncAttributeMaxDynamicSharedMemorySize, smem_out);

    // 0) weight fragment splits (independent of activations)
    wsplit_kernel<<<(WIN_NPAD * D_MODEL + 255) / 256, 256>>>(
        w_in, D_IN_PROJ, WIN_NPAD, D_MODEL, winfh, winfl);
    wsplit_kernel<<<(D_MODEL * D_INNER + 255) / 256, 256>>>(
        w_out, D_MODEL, D_MODEL, D_INNER, woutfh, woutfl);
    wsplit_kernel<<<(D_MODEL * D_MODEL + 255) / 256, 256>>>(
        mlp_w, D_MODEL, D_MODEL, D_MODEL, wmlpfh, wmlpfl);

    // 1) ln1 -> fragment
    ln_frag_kernel<<<ROWS, 128>>>(hidden, ln1_w, ln1_b, h1fh, h1fl);

    // 2) in_proj (fragment tf32 MMA)
    {
        dim3 grid(WIN_NPAD / 64, ROWS / 128);   // (37, 32)
        gemm_frag<false, false><<<grid, 256>>>(
            (const float4*)h1fh, (const float4*)h1fl,
            (const float2*)winfh, (const float2*)winfl,
            zx, D_IN_PROJ, D_IN_PROJ, D_MODEL, nullptr, nullptr);
    }

    // 3) conv + silu
    {
        int total = B_SZ * SEQ * CONV_DIM;
        conv_kernel<<<(total + 255) / 256, 256>>>(zx, conv_w, conv_b, xbc);
    }

    // 4) dt / dtA
    dt2_kernel<<<(ROWS * NHEADS + 255) / 256, 256>>>(zx, dt_bias, A_log, dtT, dtAT);

    // 5) chunked SSD
    {
        dim3 gg_(NCH, B_SZ);
        ssd_g_kernel<<<gg_, 256, smem_g>>>(xbc, Gm);

        dim3 gi(NCH, NHEADS, B_SZ);
        ssd_intra_kernel<<<gi, 256, smem_intra>>>(xbc, dtT, dtAT, Gm, D_skip,
                                                  y, Tm, Lam);

        ssd_inter_kernel<<<(NBH * HEADDIM * D_STATE / 4) / 256, 256>>>(Tm, Lam, Spm);

        ssd_out_kernel<<<gi, 256, smem_out>>>(xbc, dtAT, Spm, y);
    }

    // 6) gate + rmsnorm -> fragment
    gate_frag_kernel<<<ROWS, 256>>>(y, zx, gnorm_w, ggfh, ggfl);

    // 7) out_proj + residual (fragment tf32 MMA)
    {
        dim3 grid(D_MODEL / 64, ROWS / 128);    // (2, 32)
        gemm_frag<true, false><<<grid, 256>>>(
            (const float4*)ggfh, (const float4*)ggfl,
            (const float2*)woutfh, (const float2*)woutfl,
            res2, D_MODEL, D_MODEL, D_INNER, hidden, nullptr);
    }

    // 8) ln2 -> fragment
    ln_frag_kernel<<<ROWS, 128>>>(res2, ln2_w, ln2_b, h2fh, h2fl);

    // 9) mlp (fragment tf32 MMA)
    {
        dim3 grid(D_MODEL / 64, ROWS / 128);    // (2, 32)
        gemm_frag<false, true><<<grid, 256>>>(
            (const float4*)h2fh, (const float4*)h2fl,
            (const float2*)wmlpfh, (const float2*)wmlpfl,
            outp, D_MODEL, D_MODEL, D_MODEL, nullptr, mlp_b);
    }
    (void)in_sizes; (void)n_in; (void)out_size;
}

// round 7
// speedup vs baseline: 1.4286x; 1.3432x over previous
#include <cuda_runtime.h>
#include <cuda_bf16.h>
#include <cstdint>

#define B_SZ 2
#define SEQ 2048
#define ROWS (B_SZ * SEQ)          // 4096
#define D_MODEL 128
#define D_INNER 1024
#define NHEADS 8
#define HEADDIM 128
#define D_STATE 128
#define CONV_DIM (D_INNER + 2 * D_STATE)   // 1280
#define D_IN_PROJ (2 * D_INNER + 2 * D_STATE + NHEADS)  // 2312
#define EPS 1e-5f

#define QC 64
#define NCH (SEQ / QC)             // 32
#define NBH (B_SZ * NHEADS)        // 16

#define NT1 37                     // gemm1 n-tiles (64 each) -> 2368 >= 2312

// tcgen05 only exists in the arch-accelerated (sm_103a/sm_100a) compile pass.
#if defined(__CUDA_ARCH_FEAT_SM103_ALL) || defined(__CUDA_ARCH_FEAT_SM100_ALL) || defined(__CUDA_ARCH_FEAT_SM101_ALL)
#define HAS_TC 1
#else
#define HAS_TC 0
#endif

// ---------------- scratch ----------------
__device__ float g_zx[ROWS * D_IN_PROJ];
__device__ float g_xbc[ROWS * CONV_DIM];
__device__ float g_dtT[NBH * SEQ];
__device__ float g_dtAT[NBH * SEQ];
__device__ float g_G[B_SZ * NCH * QC * QC];
__device__ float g_T[NBH * NCH * HEADDIM * D_STATE];
__device__ float g_Sp[NBH * NCH * HEADDIM * D_STATE];
__device__ float g_Lam[NBH * NCH];
__device__ float g_y[ROWS * D_INNER];
__device__ float g_res2[ROWS * D_MODEL];

// pre-swizzled bf16 tile images (A: 128x128 = 32KB; B: 64x128 = 16KB)
__device__ __nv_bfloat16 g_af1h[ROWS * D_MODEL];
__device__ __nv_bfloat16 g_af1l[ROWS * D_MODEL];
__device__ __nv_bfloat16 g_aggh[ROWS * D_INNER];
__device__ __nv_bfloat16 g_aggl[ROWS * D_INNER];
__device__ __nv_bfloat16 g_ah2h[ROWS * D_MODEL];
__device__ __nv_bfloat16 g_ah2l[ROWS * D_MODEL];
__device__ __nv_bfloat16 g_bwinh[NT1 * 64 * D_MODEL];
__device__ __nv_bfloat16 g_bwinl[NT1 * 64 * D_MODEL];
__device__ __nv_bfloat16 g_bwouth[2 * 8 * 64 * 128];
__device__ __nv_bfloat16 g_bwoutl[2 * 8 * 64 * 128];
__device__ __nv_bfloat16 g_bwmlph[2 * 64 * 128];
__device__ __nv_bfloat16 g_bwmlpl[2 * 64 * 128];

__device__ __forceinline__ float siluf(float v) {
    return v / (1.0f + expf(-v));
}

// ---------------- tile layout (blocked SW128 atoms, 128 bf16 cols) --------
__device__ __forceinline__ int toff128(int r, int c) {   // 128-row tile
    int off = ((r >> 3) + (c >> 6) * 16) * 1024 + (r & 7) * 128 + (c & 63) * 2;
    return off ^ ((off >> 3) & 0x70);
}
__device__ __forceinline__ int toff64(int r, int c) {    // 64-row tile
    int off = ((r >> 3) + (c >> 6) * 8) * 1024 + (r & 7) * 128 + (c & 63) * 2;
    return off ^ ((off >> 3) & 0x70);
}

__device__ __forceinline__ void bf16_split(float v, uint32_t& hb, uint32_t& lb) {
    __nv_bfloat16 h = __float2bfloat16(v);
    float hf = __bfloat162float(h);
    __nv_bfloat16 l = __float2bfloat16(v - hf);
    hb = (uint32_t)__bfloat16_as_ushort(h);
    lb = (uint32_t)__bfloat16_as_ushort(l);
}

// ---------------- generic async-copy helpers (all archs) ----------------
__device__ __forceinline__ void cp_async16(void* smem_dst, const void* gsrc) {
    unsigned saddr = (unsigned)__cvta_generic_to_shared(smem_dst);
    asm volatile("cp.async.cg.shared.global [%0], [%1], 16;" :: "r"(saddr), "l"(gsrc));
}
__device__ __forceinline__ void cp_commit_wait0() {
    asm volatile("cp.async.commit_group;");
    asm volatile("cp.async.wait_group 0;");
}

#if HAS_TC
// ---------------- tcgen05 helpers (103a-only pass) ----------------
__device__ __forceinline__ bool elect1() {
    uint32_t p;
    asm volatile("{\n\t.reg .pred p;\n\telect.sync _|p, 0xFFFFFFFF;\n\t"
                 "selp.b32 %0, 1, 0, p;\n\t}" : "=r"(p));
    return p != 0;
}
__device__ __forceinline__ void tc_alloc(uint32_t smem_res, uint32_t ncols) {
    asm volatile("tcgen05.alloc.cta_group::1.sync.aligned.shared::cta.b32 [%0], %1;"
                 :: "r"(smem_res), "r"(ncols) : "memory");
}
__device__ __forceinline__ void tc_dealloc(uint32_t tmem, uint32_t ncols) {
    asm volatile("tcgen05.dealloc.cta_group::1.sync.aligned.b32 %0, %1;"
                 :: "r"(tmem), "r"(ncols));
}
__device__ __forceinline__ void mbar_init(uint32_t mbar, uint32_t cnt) {
    asm volatile("mbarrier.init.shared.b64 [%0], %1;" :: "r"(mbar), "r"(cnt) : "memory");
}
__device__ __forceinline__ void mbar_wait(uint32_t mbar, uint32_t parity) {
    uint32_t done = 0;
    while (!done) {
        asm volatile(
            "{\n\t.reg .pred p;\n\t"
            "mbarrier.try_wait.parity.acquire.cta.shared::cta.b64 p, [%1], %2, 0x989680;\n\t"
            "selp.b32 %0, 1, 0, p;\n\t}"
            : "=r"(done) : "r"(mbar), "r"(parity) : "memory");
    }
}
__device__ __forceinline__ void tc_commit(uint32_t mbar) {
    asm volatile(
        "tcgen05.commit.cta_group::1.mbarrier::arrive::one.shared::cluster.b64 [%0];"
        :: "r"(mbar) : "memory");
}
__device__ __forceinline__ void mma_f16_ss(uint32_t d, uint64_t ad, uint64_t bd,
                                           uint32_t idesc, uint32_t en) {
    asm volatile(
        "{\n\t.reg .pred p;\n\tsetp.ne.u32 p, %5, 0;\n\t"
        "tcgen05.mma.cta_group::1.kind::f16 [%0], %1, %2, %3, {%4,%4,%4,%4}, p;\n\t}"
        :: "r"(d), "l"(ad), "l"(bd), "r"(idesc), "r"(0u), "r"(en) : "memory");
}
__device__ __forceinline__ uint64_t mk_desc(uint32_t saddr) {
    // SW128, version=1 (Blackwell), SBO=64 (1024B per 8-row group), LBO=1
    return ((uint64_t)2 << 61) | ((uint64_t)1 << 46) | ((uint64_t)64 << 32)
         | ((uint64_t)1 << 16) | (uint64_t)((saddr >> 4) & 0x3FFF);
}
__device__ __forceinline__ void ldtm_x32(uint32_t* r, uint32_t addr) {
    asm volatile(
        "tcgen05.ld.sync.aligned.32x32b.x32.b32 "
        "{%0,%1,%2,%3,%4,%5,%6,%7,%8,%9,%10,%11,%12,%13,%14,%15,"
        "%16,%17,%18,%19,%20,%21,%22,%23,%24,%25,%26,%27,%28,%29,%30,%31}, [%32];"
        : "=r"(r[0]), "=r"(r[1]), "=r"(r[2]), "=r"(r[3]),
          "=r"(r[4]), "=r"(r[5]), "=r"(r[6]), "=r"(r[7]),
          "=r"(r[8]), "=r"(r[9]), "=r"(r[10]), "=r"(r[11]),
          "=r"(r[12]), "=r"(r[13]), "=r"(r[14]), "=r"(r[15]),
          "=r"(r[16]), "=r"(r[17]), "=r"(r[18]), "=r"(r[19]),
          "=r"(r[20]), "=r"(r[21]), "=r"(r[22]), "=r"(r[23]),
          "=r"(r[24]), "=r"(r[25]), "=r"(r[26]), "=r"(r[27]),
          "=r"(r[28]), "=r"(r[29]), "=r"(r[30]), "=r"(r[31])
        : "r"(addr));
}
#endif // HAS_TC

// idesc: dtype=F32, a=BF16, b=BF16, N=64, M=128
#define TC_IDESC 0x8100490u

// ---------------- GEMM: C[128m, 64n] = (Ah+Al) @ (Bh+Bl)^T (3-pass) --------
// grid (ntiles, mtiles), 128 threads. Pre-swizzled tiles: A 32KB, B 16KB.
template<bool RESID, bool BIAS>
__global__ __launch_bounds__(128) void tc_gemm(
    const __nv_bfloat16* __restrict__ Ah_, const __nv_bfloat16* __restrict__ Al_,
    const __nv_bfloat16* __restrict__ Bh_, const __nv_bfloat16* __restrict__ Bl_,
    float* __restrict__ C, int ldc, int N, int ktiles,
    const float* __restrict__ resid, const float* __restrict__ bias)
{
    extern __shared__ char smem[];
    const int tid = threadIdx.x;
    const int ntile = blockIdx.x, mtile = blockIdx.y;
    const uint32_t sbase = (uint32_t)__cvta_generic_to_shared(smem);

    const int SA_H = 1024;
    const int SA_L = SA_H + 32768;
    const int SB_H = SA_L + 32768;
    const int SB_L = SB_H + 16384;

    const char* gAh = (const char*)Ah_ + (size_t)(mtile * ktiles) * 32768;
    const char* gAl = (const char*)Al_ + (size_t)(mtile * ktiles) * 32768;
    const char* gBh = (const char*)Bh_ + (size_t)(ntile * ktiles) * 16384;
    const char* gBl = (const char*)Bl_ + (size_t)(ntile * ktiles) * 16384;

#if HAS_TC
    const int wid = tid >> 5;
    const int lane = tid & 31;
    const uint32_t mbar = sbase + 8;

    if (wid == 0) tc_alloc(sbase, 64);
    if (tid == 0) mbar_init(mbar, 1);
    __syncthreads();
    uint32_t tmem;
    asm volatile("ld.shared.b32 %0, [%1];" : "=r"(tmem) : "r"(sbase));

    for (int kt = 0; kt < ktiles; kt++) {
        const char* ah = gAh + (size_t)kt * 32768;
        const char* al = gAl + (size_t)kt * 32768;
        const char* bh = gBh + (size_t)kt * 16384;
        const char* bl = gBl + (size_t)kt * 16384;
        #pragma unroll 4
        for (int i = tid; i < 2048; i += 128) {
            cp_async16(smem + SA_H + i * 16, ah + i * 16);
            cp_async16(smem + SA_L + i * 16, al + i * 16);
        }
        #pragma unroll 4
        for (int i = tid; i < 1024; i += 128) {
            cp_async16(smem + SB_H + i * 16, bh + i * 16);
            cp_async16(smem + SB_L + i * 16, bl + i * 16);
        }
        cp_commit_wait0();
        __syncthreads();
        asm volatile("fence.proxy.async.shared::cta;" ::: "memory");

        if (wid == 0) {
            asm volatile("tcgen05.fence::after_thread_sync;" ::: "memory");
            if (elect1()) {
                uint64_t dAh = mk_desc(sbase + SA_H);
                uint64_t dAl = mk_desc(sbase + SA_L);
                uint64_t dBh = mk_desc(sbase + SB_H);
                uint64_t dBl = mk_desc(sbase + SB_L);
                #pragma unroll
                for (int ks = 0; ks < 8; ks++) {
                    uint64_t oA = (ks < 4) ? (uint64_t)(ks * 2) : (uint64_t)(1024 + (ks - 4) * 2);
                    uint64_t oB = (ks < 4) ? (uint64_t)(ks * 2) : (uint64_t)(512 + (ks - 4) * 2);
                    uint32_t en = (kt || ks) ? 1u : 0u;
                    mma_f16_ss(tmem, dAh + oA, dBh + oB, TC_IDESC, en);
                    mma_f16_ss(tmem, dAh + oA, dBl + oB, TC_IDESC, 1u);
                    mma_f16_ss(tmem, dAl + oA, dBh + oB, TC_IDESC, 1u);
                }
                tc_commit(mbar);
            }
        }
        mbar_wait(mbar, kt & 1);
    }
    asm volatile("tcgen05.fence::after_thread_sync;" ::: "memory");

    uint32_t d[64];
    ldtm_x32(d, tmem);
    ldtm_x32(d + 32, tmem + 32);
    asm volatile("tcgen05.wait::ld.sync.aligned;" ::: "memory");

    float vals[64];
    #pragma unroll
    for (int c = 0; c < 64; c++) vals[c] = __uint_as_float(d[c]);
    int row = mtile * 128 + wid * 32 + lane;
#else
    // -------- fp32 fallback (non-accelerated compile pass; insurance) -----
    float vals[64];
    #pragma unroll
    for (int c = 0; c < 64; c++) vals[c] = 0.f;

    for (int kt = 0; kt < ktiles; kt++) {
        const char* ah = gAh + (size_t)kt * 32768;
        const char* al = gAl + (size_t)kt * 32768;
        const char* bh = gBh + (size_t)kt * 16384;
        const char* bl = gBl + (size_t)kt * 16384;
        for (int i = tid; i < 2048; i += 128) {
            cp_async16(smem + SA_H + i * 16, ah + i * 16);
            cp_async16(smem + SA_L + i * 16, al + i * 16);
        }
        for (int i = tid; i < 1024; i += 128) {
            cp_async16(smem + SB_H + i * 16, bh + i * 16);
            cp_async16(smem + SB_L + i * 16, bl + i * 16);
        }
        cp_commit_wait0();
        __syncthreads();

        for (int k = 0; k < 128; k++) {
            int ao = toff128(tid, k);
            float a = __bfloat162float(*(const __nv_bfloat16*)(smem + SA_H + ao))
                    + __bfloat162float(*(const __nv_bfloat16*)(smem + SA_L + ao));
            for (int n = 0; n < 64; n++) {
                int bo = toff64(n, k);
                float b = __bfloat162float(*(const __nv_bfloat16*)(smem + SB_H + bo))
                        + __bfloat162float(*(const __nv_bfloat16*)(smem + SB_L + bo));
                vals[n] = fmaf(a, b, vals[n]);
            }
        }
        __syncthreads();
    }
    int row = mtile * 128 + tid;
#endif

    int col0 = ntile * 64;
    float* cp = C + (size_t)row * ldc + col0;
    #pragma unroll
    for (int c = 0; c < 64; c += 4) {
        int col = col0 + c;
        if (col < N) {
            float4 v = make_float4(vals[c], vals[c + 1], vals[c + 2], vals[c + 3]);
            if (RESID) {
                float4 r = *(const float4*)(resid + (size_t)row * ldc + col);
                v.x += r.x; v.y += r.y; v.z += r.z; v.w += r.w;
            }
            if (BIAS) {
                float4 b = *(const float4*)(bias + col);
                v.x += b.x; v.y += b.y; v.z += b.z; v.w += b.w;
            }
            *(float4*)(cp + c) = v;
        }
    }
#if HAS_TC
    __syncthreads();
    if (wid == 0) tc_dealloc(tmem, 64);
#endif
}

// ------------- LayerNorm -> pre-swizzled bf16 hi/lo A-tile (K=128) ---------
__global__ __launch_bounds__(128) void ln_stage_kernel(
    const float* __restrict__ x, const float* __restrict__ w,
    const float* __restrict__ b, __nv_bfloat16* __restrict__ Ah,
    __nv_bfloat16* __restrict__ Al)
{
    int row = blockIdx.x;
    int tid = threadIdx.x;
    __shared__ float sm[4];
    float v = x[(size_t)row * D_MODEL + tid];

    float s = v;
    #pragma unroll
    for (int o = 16; o; o >>= 1) s += __shfl_xor_sync(0xffffffffu, s, o);
    if ((tid & 31) == 0) sm[tid >> 5] = s;
    __syncthreads();
    float mean = (sm[0] + sm[1] + sm[2] + sm[3]) * (1.0f / 128.0f);
    __syncthreads();

    float d = v - mean;
    float q = d * d;
    #pragma unroll
    for (int o = 16; o; o >>= 1) q += __shfl_xor_sync(0xffffffffu, q, o);
    if ((tid & 31) == 0) sm[tid >> 5] = q;
    __syncthreads();
    float var = (sm[0] + sm[1] + sm[2] + sm[3]) * (1.0f / 128.0f);

    float o = d * rsqrtf(var + EPS) * w[tid] + b[tid];
    uint32_t hb, lb;
    bf16_split(o, hb, lb);
    uint32_t mine = hb | (lb << 16);
    uint32_t other = __shfl_xor_sync(0xffffffffu, mine, 1);
    if ((tid & 1) == 0) {
        uint32_t hw = (mine & 0xFFFFu) | ((other & 0xFFFFu) << 16);
        uint32_t lw = (mine >> 16) | (other & 0xFFFF0000u);
        size_t tb = (size_t)(row >> 7) * 32768;
        int off = toff128(row & 127, tid);
        *(uint32_t*)((char*)Ah + tb + off) = hw;
        *(uint32_t*)((char*)Al + tb + off) = lw;
    }
}

// ------------- W[N,K] -> pre-swizzled bf16 hi/lo B-tiles (64-row) ----------
__global__ __launch_bounds__(256) void wstage_kernel(
    const float* __restrict__ W, int Nreal, int ntiles, int K,
    __nv_bfloat16* __restrict__ Bh, __nv_bfloat16* __restrict__ Bl)
{
    int idx = blockIdx.x * 256 + threadIdx.x;
    int pairs_per_row = K >> 1;
    if (idx >= ntiles * 64 * pairs_per_row) return;
    int n = idx / pairs_per_row;
    int k0 = (idx - n * pairs_per_row) * 2;
    float v0 = (n < Nreal) ? W[(size_t)n * K + k0] : 0.f;
    float v1 = (n < Nreal) ? W[(size_t)n * K + k0 + 1] : 0.f;
    uint32_t h0, l0, h1, l1;
    bf16_split(v0, h0, l0);
    bf16_split(v1, h1, l1);
    int ktiles = K >> 7;
    size_t tb = (size_t)((n >> 6) * ktiles + (k0 >> 7)) * 16384;
    int off = toff64(n & 63, k0 & 127);
    *(uint32_t*)((char*)Bh + tb + off) = h0 | (h1 << 16);
    *(uint32_t*)((char*)Bl + tb + off) = l0 | (l1 << 16);
}

// ---------------- depthwise causal conv (k=4) + bias + silu ----------------
__global__ __launch_bounds__(256) void conv_kernel(
    const float* __restrict__ zx, const float* __restrict__ cw,
    const float* __restrict__ cb, float* __restrict__ out)
{
    int idx = blockIdx.x * 256 + threadIdx.x;
    if (idx >= B_SZ * SEQ * CONV_DIM) return;
    int c = idx % CONV_DIM;
    int t = (idx / CONV_DIM) & (SEQ - 1);
    int b = idx / (CONV_DIM * SEQ);

    const float* col = zx + (size_t)b * SEQ * D_IN_PROJ + D_INNER + c;
    float4 w = *(const float4*)(cw + c * 4);
    float acc = cb[c];
    if (t >= 3) acc = fmaf(w.x, col[(size_t)(t - 3) * D_IN_PROJ], acc);
    if (t >= 2) acc = fmaf(w.y, col[(size_t)(t - 2) * D_IN_PROJ], acc);
    if (t >= 1) acc = fmaf(w.z, col[(size_t)(t - 1) * D_IN_PROJ], acc);
    acc = fmaf(w.w, col[(size_t)t * D_IN_PROJ], acc);
    out[idx] = siluf(acc);
}

// -------- dt = softplus(raw+bias); dt and dt*A in [bh][t] layout -----------
__global__ __launch_bounds__(256) void dt2_kernel(
    const float* __restrict__ zx, const float* __restrict__ dt_bias,
    const float* __restrict__ A_log, float* __restrict__ dt_out,
    float* __restrict__ dtA_out)
{
    int idx = blockIdx.x * 256 + threadIdx.x;
    if (idx >= ROWS * NHEADS) return;
    int h = idx & (NHEADS - 1);
    int row = idx >> 3;
    int b = row >> 11;
    int t = row & (SEQ - 1);
    float raw = zx[(size_t)row * D_IN_PROJ + (D_IN_PROJ - NHEADS) + h] + dt_bias[h];
    float dt = (raw > 20.0f) ? raw : log1pf(expf(raw));
    float A = -expf(A_log[h]);
    int o = (b * NHEADS + h) * SEQ + t;
    dt_out[o] = dt;
    dtA_out[o] = dt * A;
}

// ---------------- K_G ----------------
__global__ __launch_bounds__(256) void ssd_g_kernel(
    const float* __restrict__ xbc, float* __restrict__ G)
{
    extern __shared__ float sm[];
    float* Cn = sm;
    float* Bn = sm + 128 * 68;

    int c = blockIdx.x, b = blockIdx.y;
    int tid = threadIdx.x;
    int t0 = c * QC;

    for (int q = tid; q < QC * 32; q += 256) {
        int t = q >> 5;
        int n4 = (q & 31) * 4;
        const float* row = xbc + (size_t)(b * SEQ + t0 + t) * CONV_DIM + D_INNER;
        float4 bv = *(const float4*)(row + n4);
        float4 cv = *(const float4*)(row + D_STATE + n4);
        #pragma unroll
        for (int l = 0; l < 4; l++) {
            Bn[(n4 + l) * 68 + t] = (&bv.x)[l];
            Cn[(n4 + l) * 68 + t] = (&cv.x)[l];
        }
    }
    __syncthreads();

    int ty = tid >> 4, tx = tid & 15;
    int i0 = ty * 4, j0 = tx * 4;
    float acc[4][4];
    #pragma unroll
    for (int i = 0; i < 4; i++)
        #pragma unroll
        for (int j = 0; j < 4; j++) acc[i][j] = 0.f;

    #pragma unroll 4
    for (int n = 0; n < D_STATE; n++) {
        float4 cv = *(const float4*)&Cn[n * 68 + i0];
        float4 bv = *(const float4*)&Bn[n * 68 + j0];
        float cf[4] = {cv.x, cv.y, cv.z, cv.w};
        float bf[4] = {bv.x, bv.y, bv.z, bv.w};
        #pragma unroll
        for (int i = 0; i < 4; i++)
            #pragma unroll
            for (int j = 0; j < 4; j++)
                acc[i][j] = fmaf(cf[i], bf[j], acc[i][j]);
    }

    float* Gp = G + (size_t)(b * NCH + c) * QC * QC;
    #pragma unroll
    for (int i = 0; i < 4; i++) {
        float4 v = make_float4(acc[i][0], acc[i][1], acc[i][2], acc[i][3]);
        *(float4*)(Gp + (i0 + i) * QC + j0) = v;
    }
}

// ---------------- K_intra ----------------
__global__ __launch_bounds__(256) void ssd_intra_kernel(
    const float* __restrict__ xbc, const float* __restrict__ dt_t,
    const float* __restrict__ dtA_t, const float* __restrict__ G,
    const float* __restrict__ D_skip,
    float* __restrict__ y_out, float* __restrict__ T_out,
    float* __restrict__ Lam_out)
{
    extern __shared__ float sm[];
    float* Wt = sm;
    float* Xj = Wt + QC * 68;
    float* Bj = Xj + QC * 132;
    float* s_cs = Bj + QC * 132;
    float* s_dt = s_cs + QC;
    float* s_el = s_dt + QC;

    int c = blockIdx.x, h = blockIdx.y, b = blockIdx.z;
    int tid = threadIdx.x;
    int bh = b * NHEADS + h;
    int t0 = c * QC;

    if (tid < QC) {
        s_cs[tid] = dtA_t[(size_t)bh * SEQ + t0 + tid];
        s_dt[tid] = dt_t[(size_t)bh * SEQ + t0 + tid];
    }
    __syncthreads();
    #pragma unroll
    for (int off = 1; off < QC; off <<= 1) {
        float v = 0.f;
        if (tid < QC && tid >= off) v = s_cs[tid - off];
        __syncthreads();
        if (tid < QC) s_cs[tid] += v;
        __syncthreads();
    }
    if (tid < QC) s_el[tid] = __expf(s_cs[QC - 1] - s_cs[tid]) * s_dt[tid];
    if (tid == 0) Lam_out[bh * NCH + c] = __expf(s_cs[QC - 1]);

    for (int q = tid; q < QC * 32; q += 256) {
        int t = q >> 5;
        int n4 = (q & 31) * 4;
        const float* row = xbc + (size_t)(b * SEQ + t0 + t) * CONV_DIM;
        *(float4*)&Xj[t * 132 + n4] = *(const float4*)(row + h * HEADDIM + n4);
        *(float4*)&Bj[t * 132 + n4] = *(const float4*)(row + D_INNER + n4);
    }

    int ty = tid >> 4, tx = tid & 15;
    {
        int i0 = ty * 4, j0 = tx * 4;
        const float* Gp = G + (size_t)(b * NCH + c) * QC * QC;
        #pragma unroll
        for (int ii = 0; ii < 4; ii++) {
            int i = i0 + ii;
            float4 gv = *(const float4*)(Gp + i * QC + j0);
            float gf[4] = {gv.x, gv.y, gv.z, gv.w};
            #pragma unroll
            for (int jj = 0; jj < 4; jj++) {
                int j = j0 + jj;
                float w = 0.f;
                if (j <= i) w = __expf(s_cs[i] - s_cs[j]) * s_dt[j] * gf[jj];
                Wt[j * 68 + i] = w;
            }
        }
    }
    __syncthreads();

    float Dsk = D_skip[h];

    {
        int i0 = ty * 4, p0 = tx * 8;
        float acc[4][8];
        #pragma unroll
        for (int i = 0; i < 4; i++)
            #pragma unroll
            for (int p = 0; p < 8; p++) acc[i][p] = 0.f;

        int jmax = i0 + 4;
        for (int j = 0; j < jmax; j++) {
            float4 wv = *(const float4*)&Wt[j * 68 + i0];
            float4 xa = *(const float4*)&Xj[j * 132 + p0];
            float4 xb = *(const float4*)&Xj[j * 132 + p0 + 4];
            float wf[4] = {wv.x, wv.y, wv.z, wv.w};
            float xf[8] = {xa.x, xa.y, xa.z, xa.w, xb.x, xb.y, xb.z, xb.w};
            #pragma unroll
            for (int i = 0; i < 4; i++)
                #pragma unroll
                for (int p = 0; p < 8; p++)
                    acc[i][p] = fmaf(wf[i], xf[p], acc[i][p]);
        }
        #pragma unroll
        for (int ii = 0; ii < 4; ii++) {
            int i = i0 + ii;
            size_t row = (size_t)(b * SEQ + t0 + i);
            float* yp = y_out + row * D_INNER + h * HEADDIM + p0;
            float4 x0 = *(const float4*)&Xj[i * 132 + p0];
            float4 x1 = *(const float4*)&Xj[i * 132 + p0 + 4];
            float4 o0 = make_float4(fmaf(Dsk, x0.x, acc[ii][0]),
                                    fmaf(Dsk, x0.y, acc[ii][1]),
                                    fmaf(Dsk, x0.z, acc[ii][2]),
                                    fmaf(Dsk, x0.w, acc[ii][3]));
            float4 o1 = make_float4(fmaf(Dsk, x1.x, acc[ii][4]),
                                    fmaf(Dsk, x1.y, acc[ii][5]),
                                    fmaf(Dsk, x1.z, acc[ii][6]),
                                    fmaf(Dsk, x1.w, acc[ii][7]));
            *(float4*)yp = o0;
            *(float4*)(yp + 4) = o1;
        }
    }

    {
        int p0 = ty * 8, n0 = tx * 8;
        float acc[8][8];
        #pragma unroll
        for (int p = 0; p < 8; p++)
            #pragma unroll
            for (int n = 0; n < 8; n++) acc[p][n] = 0.f;

        #pragma unroll 2
        for (int j = 0; j < QC; j++) {
            float el = s_el[j];
            float4 xa = *(const float4*)&Xj[j * 132 + p0];
            float4 xb = *(const float4*)&Xj[j * 132 + p0 + 4];
            float4 ba = *(const float4*)&Bj[j * 132 + n0];
            float4 bb = *(const float4*)&Bj[j * 132 + n0 + 4];
            float xf[8] = {el * xa.x, el * xa.y, el * xa.z, el * xa.w,
                           el * xb.x, el * xb.y, el * xb.z, el * xb.w};
            float bf[8] = {ba.x, ba.y, ba.z, ba.w, bb.x, bb.y, bb.z, bb.w};
            #pragma unroll
            for (int p = 0; p < 8; p++)
                #pragma unroll
                for (int n = 0; n < 8; n++)
                    acc[p][n] = fmaf(xf[p], bf[n], acc[p][n]);
        }
        float* Tp = T_out + ((size_t)bh * NCH + c) * (HEADDIM * D_STATE);
        #pragma unroll
        for (int pp = 0; pp < 8; pp++) {
            float4 v0 = make_float4(acc[pp][0], acc[pp][1], acc[pp][2], acc[pp][3]);
            float4 v1 = make_float4(acc[pp][4], acc[pp][5], acc[pp][6], acc[pp][7]);
            *(float4*)(Tp + (p0 + pp) * D_STATE + n0) = v0;
            *(float4*)(Tp + (p0 + pp) * D_STATE + n0 + 4) = v1;
        }
    }
}

// ---------------- K_inter ----------------
__global__ __launch_bounds__(256) void ssd_inter_kernel(
    const float* __restrict__ T, const float* __restrict__ Lam,
    float* __restrict__ Sp)
{
    int gid = blockIdx.x * 256 + threadIdx.x;
    int bh = gid >> 12;
    int pn = gid & 4095;
    const float4* Tb = (const float4*)(T + ((size_t)bh << 19)) + pn;
    float4* Sb = (float4*)(Sp + ((size_t)bh << 19)) + pn;
    const float* Lb = Lam + bh * NCH;

    float4 S = make_float4(0.f, 0.f, 0.f, 0.f);
    #pragma unroll 4
    for (int c = 0; c < NCH; c++) {
        if (c) Sb[(size_t)c << 12] = S;
        float4 Tv = Tb[(size_t)c << 12];
        float lam = Lb[c];
        S.x = fmaf(lam, S.x, Tv.x);
        S.y = fmaf(lam, S.y, Tv.y);
        S.z = fmaf(lam, S.z, Tv.z);
        S.w = fmaf(lam, S.w, Tv.w);
    }
}

// ---------------- K_out ----------------
__global__ __launch_bounds__(256) void ssd_out_kernel(
    const float* __restrict__ xbc, const float* __restrict__ dtA_t,
    const float* __restrict__ Sp, float* __restrict__ y_out)
{
    int c = blockIdx.x;
    if (c == 0) return;
    extern __shared__ float sm[];
    float* Cn = sm;
    float* Spn = Cn + 128 * 68;
    float* s_cs = Spn + 128 * 132;

    int h = blockIdx.y, b = blockIdx.z;
    int tid = threadIdx.x;
    int bh = b * NHEADS + h;
    int t0 = c * QC;

    if (tid < QC) s_cs[tid] = dtA_t[(size_t)bh * SEQ + t0 + tid];
    __syncthreads();
    #pragma unroll
    for (int off = 1; off < QC; off <<= 1) {
        float v = 0.f;
        if (tid < QC && tid >= off) v = s_cs[tid - off];
        __syncthreads();
        if (tid < QC) s_cs[tid] += v;
        __syncthreads();
    }

    for (int q = tid; q < QC * 32; q += 256) {
        int t = q >> 5;
        int n4 = (q & 31) * 4;
        const float* row = xbc + (size_t)(b * SEQ + t0 + t) * CONV_DIM
                         + D_INNER + D_STATE;
        float4 v = *(const float4*)(row + n4);
        #pragma unroll
        for (int l = 0; l < 4; l++) Cn[(n4 + l) * 68 + t] = (&v.x)[l];
    }
    const float* Spsrc = Sp + ((size_t)bh * NCH + c) * (HEADDIM * D_STATE);
    for (int q = tid; q < HEADDIM * 32; q += 256) {
        int p = q >> 5;
        int n4 = (q & 31) * 4;
        float4 v = *(const float4*)(Spsrc + p * D_STATE + n4);
        #pragma unroll
        for (int l = 0; l < 4; l++) Spn[(n4 + l) * 132 + p] = (&v.x)[l];
    }
    __syncthreads();

    int ty = tid >> 4, tx = tid & 15;
    int i0 = ty * 4, p0 = tx * 8;
    float acc[4][8];
    #pragma unroll
    for (int i = 0; i < 4; i++)
        #pragma unroll
        for (int p = 0; p < 8; p++) acc[i][p] = 0.f;

    #pragma unroll 2
    for (int n = 0; n < D_STATE; n++) {
        float4 cv = *(const float4*)&Cn[n * 68 + i0];
        float4 sa = *(const float4*)&Spn[n * 132 + p0];
        float4 sb = *(const float4*)&Spn[n * 132 + p0 + 4];
        float cf[4] = {cv.x, cv.y, cv.z, cv.w};
        float sf[8] = {sa.x, sa.y, sa.z, sa.w, sb.x, sb.y, sb.z, sb.w};
        #pragma unroll
        for (int i = 0; i < 4; i++)
            #pragma unroll
            for (int p = 0; p < 8; p++)
                acc[i][p] = fmaf(cf[i], sf[p], acc[i][p]);
    }

    #pragma unroll
    for (int ii = 0; ii < 4; ii++) {
        int i = i0 + ii;
        float e = __expf(s_cs[i]);
        size_t row = (size_t)(b * SEQ + t0 + i);
        float* yp = y_out + row * D_INNER + h * HEADDIM + p0;
        float4 y0 = *(const float4*)yp;
        float4 y1 = *(const float4*)(yp + 4);
        y0.x = fmaf(e, acc[ii][0], y0.x);
        y0.y = fmaf(e, acc[ii][1], y0.y);
        y0.z = fmaf(e, acc[ii][2], y0.z);
        y0.w = fmaf(e, acc[ii][3], y0.w);
        y1.x = fmaf(e, acc[ii][4], y1.x);
        y1.y = fmaf(e, acc[ii][5], y1.y);
        y1.z = fmaf(e, acc[ii][6], y1.z);
        y1.w = fmaf(e, acc[ii][7], y1.w);
        *(float4*)yp = y0;
        *(float4*)(yp + 4) = y1;
    }
}

// ---- gate + RMSNorm -> pre-swizzled bf16 hi/lo A-tiles (K=1024) -----------
__global__ __launch_bounds__(256) void gate_stage_kernel(
    const float* __restrict__ y, const float* __restrict__ zx,
    const float* __restrict__ gw, __nv_bfloat16* __restrict__ Ah,
    __nv_bfloat16* __restrict__ Al)
{
    int row = blockIdx.x;
    int tid = threadIdx.x;
    int d = tid * 4;
    __shared__ float sm[8];

    float4 y4 = *(const float4*)(y + (size_t)row * D_INNER + d);
    float4 z4 = *(const float4*)(zx + (size_t)row * D_IN_PROJ + d);
    float g0 = y4.x * siluf(z4.x);
    float g1 = y4.y * siluf(z4.y);
    float g2 = y4.z * siluf(z4.z);
    float g3 = y4.w * siluf(z4.w);

    float ss = g0 * g0 + g1 * g1 + g2 * g2 + g3 * g3;
    #pragma unroll
    for (int o = 16; o; o >>= 1) ss += __shfl_xor_sync(0xffffffffu, ss, o);
    if ((tid & 31) == 0) sm[tid >> 5] = ss;
    __syncthreads();
    float tot = 0.f;
    #pragma unroll
    for (int i = 0; i < 8; i++) tot += sm[i];
    float scale = rsqrtf(tot * (1.0f / (float)D_INNER) + EPS);

    float4 w4 = *(const float4*)(gw + d);
    float v0 = g0 * scale * w4.x, v1 = g1 * scale * w4.y;
    float v2 = g2 * scale * w4.z, v3 = g3 * scale * w4.w;

    uint32_t h0, l0, h1, l1, h2, l2, h3, l3;
    bf16_split(v0, h0, l0);
    bf16_split(v1, h1, l1);
    bf16_split(v2, h2, l2);
    bf16_split(v3, h3, l3);

    int ktile = d >> 7;
    int cl = d & 127;
    size_t tb = (size_t)((row >> 7) * 8 + ktile) * 32768;
    int r = row & 127;
    int off0 = toff128(r, cl);
    int off1 = toff128(r, cl + 2);
    *(uint32_t*)((char*)Ah + tb + off0) = h0 | (h1 << 16);
    *(uint32_t*)((char*)Al + tb + off0) = l0 | (l1 << 16);
    *(uint32_t*)((char*)Ah + tb + off1) = h2 | (h3 << 16);
    *(uint32_t*)((char*)Al + tb + off1) = l2 | (l3 << 16);
}

// ---------------- launch ----------------
extern "C" void kernel_launch(void* const* d_in, const int* in_sizes, int n_in,
                              void* d_out, int out_size)
{
    const float* hidden  = (const float*)d_in[0];
    const float* w_in    = (const float*)d_in[1];
    const float* conv_w  = (const float*)d_in[2];
    const float* conv_b  = (const float*)d_in[3];
    const float* dt_bias = (const float*)d_in[4];
    const float* A_log   = (const float*)d_in[5];
    const float* D_skip  = (const float*)d_in[6];
    const float* gnorm_w = (const float*)d_in[7];
    const float* w_out   = (const float*)d_in[8];
    const float* ln1_w   = (const float*)d_in[9];
    const float* ln1_b   = (const float*)d_in[10];
    const float* ln2_w   = (const float*)d_in[11];
    const float* ln2_b   = (const float*)d_in[12];
    const float* mlp_w   = (const float*)d_in[13];
    const float* mlp_b   = (const float*)d_in[14];
    float* outp = (float*)d_out;

    float *zx, *xbc, *dtT, *dtAT, *Gm, *Tm, *Spm, *Lam, *y, *res2;
    __nv_bfloat16 *af1h, *af1l, *aggh, *aggl, *ah2h, *ah2l;
    __nv_bfloat16 *bwinh, *bwinl, *bwouth, *bwoutl, *bwmlph, *bwmlpl;
    cudaGetSymbolAddress((void**)&zx,   g_zx);
    cudaGetSymbolAddress((void**)&xbc,  g_xbc);
    cudaGetSymbolAddress((void**)&dtT,  g_dtT);
    cudaGetSymbolAddress((void**)&dtAT, g_dtAT);
    cudaGetSymbolAddress((void**)&Gm,   g_G);
    cudaGetSymbolAddress((void**)&Tm,   g_T);
    cudaGetSymbolAddress((void**)&Spm,  g_Sp);
    cudaGetSymbolAddress((void**)&Lam,  g_Lam);
    cudaGetSymbolAddress((void**)&y,    g_y);
    cudaGetSymbolAddress((void**)&res2, g_res2);
    cudaGetSymbolAddress((void**)&af1h, g_af1h);
    cudaGetSymbolAddress((void**)&af1l, g_af1l);
    cudaGetSymbolAddress((void**)&aggh, g_aggh);
    cudaGetSymbolAddress((void**)&aggl, g_aggl);
    cudaGetSymbolAddress((void**)&ah2h, g_ah2h);
    cudaGetSymbolAddress((void**)&ah2l, g_ah2l);
    cudaGetSymbolAddress((void**)&bwinh, g_bwinh);
    cudaGetSymbolAddress((void**)&bwinl, g_bwinl);
    cudaGetSymbolAddress((void**)&bwouth, g_bwouth);
    cudaGetSymbolAddress((void**)&bwoutl, g_bwoutl);
    cudaGetSymbolAddress((void**)&bwmlph, g_bwmlph);
    cudaGetSymbolAddress((void**)&bwmlpl, g_bwmlpl);

    const int smem_gemm  = 1024 + 32768 * 2 + 16384 * 2;   // 99328
    const int smem_g     = (128 * 68 * 2) * 4;
    const int smem_intra = (QC * 68 + QC * 132 * 2 + 3 * QC) * 4;
    const int smem_out   = (128 * 68 + 128 * 132 + QC) * 4;
    cudaFuncSetAttribute(tc_gemm<false, false>,
        cudaFuncAttributeMaxDynamicSharedMemorySize, smem_gemm);
    cudaFuncSetAttribute(tc_gemm<true, false>,
        cudaFuncAttributeMaxDynamicSharedMemorySize, smem_gemm);
    cudaFuncSetAttribute(tc_gemm<false, true>,
        cudaFuncAttributeMaxDynamicSharedMemorySize, smem_gemm);
    cudaFuncSetAttribute(ssd_g_kernel,
        cudaFuncAttributeMaxDynamicSharedMemorySize, smem_g);
    cudaFuncSetAttribute(ssd_intra_kernel,
        cudaFuncAttributeMaxDynamicSharedMemorySize, smem_intra);
    cudaFuncSetAttribute(ssd_out_kernel,
        cudaFuncAttributeMaxDynamicSharedMemorySize, smem_out);

    // 0) weight stages
    wstage_kernel<<<(NT1 * 64 * 64 + 255) / 256, 256>>>(
        w_in, D_IN_PROJ, NT1, D_MODEL, bwinh, bwinl);
    wstage_kernel<<<(2 * 64 * 512 + 255) / 256, 256>>>(
        w_out, D_MODEL, 2, D_INNER, bwouth, bwoutl);
    wstage_kernel<<<(2 * 64 * 64 + 255) / 256, 256>>>(
        mlp_w, D_MODEL, 2, D_MODEL, bwmlph, bwmlpl);

    // 1) ln1 -> bf16 tiles
    ln_stage_kernel<<<ROWS, 128>>>(hidden, ln1_w, ln1_b, af1h, af1l);

    // 2) in_proj (tcgen05)
    {
        dim3 grid(NT1, ROWS / 128);
        tc_gemm<false, false><<<grid, 128, smem_gemm>>>(
            af1h, af1l, bwinh, bwinl, zx, D_IN_PROJ, D_IN_PROJ, 1,
            nullptr, nullptr);
    }

    // 3) conv + silu
    {
        int total = B_SZ * SEQ * CONV_DIM;
        conv_kernel<<<(total + 255) / 256, 256>>>(zx, conv_w, conv_b, xbc);
    }

    // 4) dt / dtA
    dt2_kernel<<<(ROWS * NHEADS + 255) / 256, 256>>>(zx, dt_bias, A_log, dtT, dtAT);

    // 5) chunked SSD
    {
        dim3 gg_(NCH, B_SZ);
        ssd_g_kernel<<<gg_, 256, smem_g>>>(xbc, Gm);
        dim3 gi(NCH, NHEADS, B_SZ);
        ssd_intra_kernel<<<gi, 256, smem_intra>>>(xbc, dtT, dtAT, Gm, D_skip,
                                                  y, Tm, Lam);
        ssd_inter_kernel<<<(NBH * HEADDIM * D_STATE / 4) / 256, 256>>>(Tm, Lam, Spm);
        ssd_out_kernel<<<gi, 256, smem_out>>>(xbc, dtAT, Spm, y);
    }

    // 6) gate + rmsnorm -> bf16 tiles
    gate_stage_kernel<<<ROWS, 256>>>(y, zx, gnorm_w, aggh, aggl);

    // 7) out_proj + residual (tcgen05, K-loop 8)
    {
        dim3 grid(2, ROWS / 128);
        tc_gemm<true, false><<<grid, 128, smem_gemm>>>(
            aggh, aggl, bwouth, bwoutl, res2, D_MODEL, D_MODEL, 8,
            hidden, nullptr);
    }

    // 8) ln2 -> bf16 tiles
    ln_stage_kernel<<<ROWS, 128>>>(res2, ln2_w, ln2_b, ah2h, ah2l);

    // 9) mlp (tcgen05)
    {
        dim3 grid(2, ROWS / 128);
        tc_gemm<false, true><<<grid, 128, smem_gemm>>>(
            ah2h, ah2l, bwmlph, bwmlpl, outp, D_MODEL, D_MODEL, 1,
            nullptr, mlp_b);
    }
    (void)in_sizes; (void)n_in; (void)out_size;
}